// round 5
// baseline (speedup 1.0000x reference)
#include <cuda_runtime.h>
#include <cstdint>

#define B_ 8
#define T_ 2048
#define C_ 1024
#define H_ 64
#define M_ (B_*T_)   // 16384

__device__ float g_q[M_*H_];
__device__ float g_k[M_*H_];
__device__ float g_v[M_*H_];
// split-K attention partials
__device__ float g_po[2*M_*H_];
__device__ float g_ml[2*M_*2];

__device__ __forceinline__ float tf32r(float x){
    asm("cvt.rna.tf32.f32 %0, %0;" : "+f"(x));
    return x;
}

__device__ __forceinline__ void mma_tf32(float* d, const float* a, const float* b, const float* c){
    asm volatile("mma.sync.aligned.m16n8k8.row.col.f32.tf32.tf32.f32 "
        "{%0,%1,%2,%3}, {%4,%5,%6,%7}, {%8,%9}, {%10,%11,%12,%13};"
        : "=f"(d[0]),"=f"(d[1]),"=f"(d[2]),"=f"(d[3])
        : "r"(__float_as_uint(a[0])),"r"(__float_as_uint(a[1])),
          "r"(__float_as_uint(a[2])),"r"(__float_as_uint(a[3])),
          "r"(__float_as_uint(b[0])),"r"(__float_as_uint(b[1])),
          "f"(c[0]),"f"(c[1]),"f"(c[2]),"f"(c[3]));
}

// ---------------------------------------------------------------------------
// Fused QKV projection, tf32 mma, BM=128 BN=192 BK=32, grid 128, 8 warps.
// SMEM holds operands PRE-PACKED in mma-fragment order:
//   A4[(kk*4+q)*64 + wm*16+mi*8+g] = {A[R][k],A[R+8][k],A[R][k+4],A[R+8][k+4]}
//   B4[(kk*4+q)*96 + t*8+g]        = {b0(2t),b1(2t),b0(2t+1),b1(2t+1)}
// so each fragment read is one conflict-free LDS.128.
// ---------------------------------------------------------------------------
#define QKV_A_F (128*32)        // 4096 floats per buffer
#define QKV_B_F (32*192)        // 6144 floats per buffer
#define QKV_SMEM ((2*QKV_A_F + 2*QKV_B_F)*4)   // 81920 B

__global__ __launch_bounds__(256) void qkv_kernel(
    const float* __restrict__ x, const float* __restrict__ wq,
    const float* __restrict__ wk, const float* __restrict__ wv)
{
    extern __shared__ float sm[];
    float* A0 = sm;
    float* B0 = sm + 2*QKV_A_F;

    const int tid  = threadIdx.x;
    const int lane = tid & 31, warp = tid >> 5;
    const int wm = warp & 3, wn = warp >> 2;
    const int g = lane >> 2, q = lane & 3;
    const int m0 = blockIdx.x * 128;

    float acc[2][12][4];
    #pragma unroll
    for (int mi=0;mi<2;mi++)
        #pragma unroll
        for (int j=0;j<12;j++){acc[mi][j][0]=acc[mi][j][1]=acc[mi][j][2]=acc[mi][j][3]=0.f;}

    float4 xs[4], ws[3][2];

#define QKV_LOAD(K0) do { \
    _Pragma("unroll") \
    for (int it=0; it<4; it++){ \
        int i = tid + it*256; int r = i>>3, c4 = (i&7)*4; \
        xs[it] = *(const float4*)&x[(size_t)(m0+r)*C_ + (K0) + c4]; \
    } \
    _Pragma("unroll") \
    for (int it=0; it<2; it++){ \
        int i = tid + it*256; int r = i>>4, c4 = (i&15)*4; \
        int gi = ((K0)+r)*H_ + c4; \
        ws[0][it] = *(const float4*)&wq[gi]; \
        ws[1][it] = *(const float4*)&wk[gi]; \
        ws[2][it] = *(const float4*)&wv[gi]; \
    } } while(0)

    // pack-store: scatter each loaded element to its fragment slot
#define QKV_STORE(BUF) do { \
    float* A  = A0 + (BUF)*QKV_A_F; \
    float* Bb = B0 + (BUF)*QKV_B_F; \
    _Pragma("unroll") \
    for (int it=0; it<4; it++){ \
        int i = tid + it*256; int r = i>>3, c4 = (i&7)*4; \
        int base = (r>>5)*16 + ((r>>4)&1)*8 + (r&7); \
        int h = (r>>3)&1; \
        const float* xe = (const float*)&xs[it]; \
        _Pragma("unroll") \
        for (int e=0;e<4;e++){ \
            int k = c4 + e; \
            int kk = k>>3, qq = k&3, hi = (k>>2)&1; \
            A[((kk*4+qq)*64 + base)*4 + h + 2*hi] = tf32r(xe[e]); \
        } \
    } \
    _Pragma("unroll") \
    for (int it=0; it<2; it++){ \
        int i = tid + it*256; int r = i>>4, c4 = (i&15)*4; \
        int kk = r>>3, qq = r&3, hi = (r>>2)&1; \
        _Pragma("unroll") \
        for (int m=0;m<3;m++){ \
            const float* we = (const float*)&ws[m][it]; \
            _Pragma("unroll") \
            for (int e=0;e<4;e++){ \
                int n = m*64 + c4 + e; \
                int t = n>>4, jp = (n>>3)&1, g2 = n&7; \
                Bb[((kk*4+qq)*96 + t*8 + g2)*4 + hi + 2*jp] = tf32r(we[e]); \
            } \
        } \
    } } while(0)

#define QKV_COMPUTE(BUF) do { \
    const float* A  = A0 + (BUF)*QKV_A_F; \
    const float* Bb = B0 + (BUF)*QKV_B_F; \
    _Pragma("unroll") \
    for (int kk=0;kk<4;kk++){ \
        float4 av0 = *(const float4*)&A[((kk*4+q)*64 + wm*16 + g)*4]; \
        float4 av1 = *(const float4*)&A[((kk*4+q)*64 + wm*16 + 8 + g)*4]; \
        _Pragma("unroll") \
        for (int tl=0;tl<6;tl++){ \
            float4 bv = *(const float4*)&Bb[((kk*4+q)*96 + (wn*6+tl)*8 + g)*4]; \
            mma_tf32(acc[0][2*tl],   (const float*)&av0, &bv.x, acc[0][2*tl]); \
            mma_tf32(acc[0][2*tl+1], (const float*)&av0, &bv.z, acc[0][2*tl+1]); \
            mma_tf32(acc[1][2*tl],   (const float*)&av1, &bv.x, acc[1][2*tl]); \
            mma_tf32(acc[1][2*tl+1], (const float*)&av1, &bv.z, acc[1][2*tl+1]); \
        } \
    } } while(0)

    QKV_LOAD(0);
    QKV_STORE(0);
    __syncthreads();

    #pragma unroll 1
    for (int c = 0; c < 32; c++){
        const int cur = c & 1;
        if (c < 31) QKV_LOAD((c+1) << 5);
        QKV_COMPUTE(cur);
        if (c < 31){
            QKV_STORE(cur ^ 1);
            __syncthreads();
        }
    }

    // epilogue: scatter to g_q/g_k/g_v; fold C^-0.5 into q
    #pragma unroll
    for (int mi=0;mi<2;mi++){
        #pragma unroll
        for (int j=0;j<12;j++){
            int n  = wn*96 + j*8 + q*2;
            int r0 = m0 + wm*32 + mi*16 + g;
            float sc   = (n < 64) ? 0.03125f : 1.f;
            float* dst = (n < 64) ? g_q : ((n < 128) ? g_k : g_v);
            int nn     = (n < 64) ? n   : ((n < 128) ? n-64 : n-128);
            *(float2*)&dst[(size_t)r0*H_ + nn]     = make_float2(acc[mi][j][0]*sc, acc[mi][j][1]*sc);
            *(float2*)&dst[(size_t)(r0+8)*H_ + nn] = make_float2(acc[mi][j][2]*sc, acc[mi][j][3]*sc);
        }
    }
}

// ---------------------------------------------------------------------------
// Flash attention (causal), tf32 mma, cross-CTA split-K by 2, packed frags.
//   K4[(kk*4+q)*32 + t*8+g] = {K[n0][k],K[n0][k+4],K[n0+8][k],K[n0+8][k+4]}
//   V4[(kk*4+q)*32 + t*8+g] = {V[k][n0],V[k+4][n0],V[k][n0+8],V[k+4][n0+8]}
//   P4[(j*4+qa)*32 + w*8+g] = {P[r][c],P[r+8][c],P[r][c+4],P[r+8][c+4]}, c=j*8+qa
// ---------------------------------------------------------------------------
#define QS_STRIDE 68
#define ATTN_P_F (64*QS_STRIDE)      // 4352 floats (Q staging, then packed P: 4096)
#define ATTN_SMEM ((ATTN_P_F + 4096 + 4096)*4)   // 50176 B

__global__ __launch_bounds__(128) void attn_kernel()
{
    extern __shared__ float sm[];
    float* Qs = sm;                  // Q staging, then packed P
    float* K4 = sm + ATTN_P_F;
    float* V4 = K4 + 4096;

    const int tid  = threadIdx.x;
    const int lane = tid & 31, w = tid >> 5;
    const int g = lane >> 2, q = lane & 3;
    const int qt = 31 - blockIdx.x;
    const int b  = blockIdx.y;
    const int s  = blockIdx.z;
    const int q0 = qt * 64;

    const float* Qg = g_q + ((size_t)b*T_ + q0)*H_;
    const float* Kg = g_k + (size_t)b*T_*H_;
    const float* Vg = g_v + (size_t)b*T_*H_;

    // stage Q (tf32), plain layout, then hoist fragments
    #pragma unroll
    for (int it=0; it<8; it++){
        int i = tid + it*128;
        int r = i>>4, c4 = (i&15)*4;
        float4 v = *(const float4*)&Qg[(size_t)r*H_ + c4];
        v.x=tf32r(v.x); v.y=tf32r(v.y); v.z=tf32r(v.z); v.w=tf32r(v.w);
        *(float4*)&Qs[r*QS_STRIDE + c4] = v;
    }
    __syncthreads();

    float qa[8][4];
    #pragma unroll
    for (int kk=0;kk<8;kk++){
        int base = (w*16+g)*QS_STRIDE + kk*8 + q;
        qa[kk][0]=Qs[base];
        qa[kk][1]=Qs[base + 8*QS_STRIDE];
        qa[kk][2]=Qs[base + 4];
        qa[kk][3]=Qs[base + 8*QS_STRIDE + 4];
    }
    __syncthreads();   // Qs region now reusable as packed P

    float O[8][4];
    #pragma unroll
    for (int j=0;j<8;j++){O[j][0]=O[j][1]=O[j][2]=O[j][3]=0.f;}
    float m0r=-1e30f, m1r=-1e30f, l0=0.f, l1=0.f;

    #pragma unroll 1
    for (int jt = s; jt <= qt; jt += 2){
        __syncthreads();
        const int k0 = jt*64;
        // load + pack K and V
        #pragma unroll
        for (int it=0; it<8; it++){
            int i = tid + it*128;
            int r = i>>4, c4 = (i&15)*4;
            float4 kvec = *(const float4*)&Kg[(size_t)(k0+r)*H_ + c4];
            float4 vvec = *(const float4*)&Vg[(size_t)(k0+r)*H_ + c4];
            const float* ke = (const float*)&kvec;
            const float* ve = (const float*)&vvec;
            // K: n=r (key row), k=c (head dim)
            {
                int t = r>>4, jp = (r>>3)&1, g2 = r&7;
                #pragma unroll
                for (int e=0;e<4;e++){
                    int c = c4+e;
                    int kk = c>>3, qq = c&3, hi = (c>>2)&1;
                    K4[((kk*4+qq)*32 + t*8 + g2)*4 + hi + 2*jp] = tf32r(ke[e]);
                }
            }
            // V: k=r (key), n=c (head dim)
            {
                int kk = r>>3, qq = r&3, hi = (r>>2)&1;
                #pragma unroll
                for (int e=0;e<4;e++){
                    int c = c4+e;
                    int t = c>>4, jp = (c>>3)&1, g2 = c&7;
                    V4[((kk*4+qq)*32 + t*8 + g2)*4 + hi + 2*jp] = tf32r(ve[e]);
                }
            }
        }
        __syncthreads();

        // S = Q K^T
        float sreg[8][4];
        #pragma unroll
        for (int j=0;j<8;j++){sreg[j][0]=sreg[j][1]=sreg[j][2]=sreg[j][3]=0.f;}
        #pragma unroll
        for (int kk=0;kk<8;kk++){
            #pragma unroll
            for (int t=0;t<4;t++){
                float4 bv = *(const float4*)&K4[((kk*4+q)*32 + t*8 + g)*4];
                mma_tf32(sreg[2*t],   qa[kk], &bv.x, sreg[2*t]);
                mma_tf32(sreg[2*t+1], qa[kk], &bv.z, sreg[2*t+1]);
            }
        }

        if (jt == qt){   // diagonal tile → causal mask
            #pragma unroll
            for (int j=0;j<8;j++){
                int c0 = j*8 + 2*q, c1 = c0+1;
                int r0l = w*16+g, r1l = r0l+8;
                if (c0 > r0l) sreg[j][0] = -1e30f;
                if (c1 > r0l) sreg[j][1] = -1e30f;
                if (c0 > r1l) sreg[j][2] = -1e30f;
                if (c1 > r1l) sreg[j][3] = -1e30f;
            }
        }

        // online softmax
        float mx0=-1e30f, mx1=-1e30f;
        #pragma unroll
        for (int j=0;j<8;j++){
            mx0 = fmaxf(mx0, fmaxf(sreg[j][0], sreg[j][1]));
            mx1 = fmaxf(mx1, fmaxf(sreg[j][2], sreg[j][3]));
        }
        mx0 = fmaxf(mx0, __shfl_xor_sync(0xffffffffu, mx0, 1));
        mx0 = fmaxf(mx0, __shfl_xor_sync(0xffffffffu, mx0, 2));
        mx1 = fmaxf(mx1, __shfl_xor_sync(0xffffffffu, mx1, 1));
        mx1 = fmaxf(mx1, __shfl_xor_sync(0xffffffffu, mx1, 2));

        float mn0 = fmaxf(m0r, mx0), mn1 = fmaxf(m1r, mx1);
        float al0 = __expf(m0r - mn0), al1 = __expf(m1r - mn1);
        m0r = mn0; m1r = mn1;
        l0 *= al0; l1 *= al1;

        float rs0=0.f, rs1=0.f;
        const int pbase = 2*(q>>1);                   // elem offset (col+4 flag)
        #pragma unroll
        for (int j=0;j<8;j++){
            float p0 = __expf(sreg[j][0]-mn0), p1 = __expf(sreg[j][1]-mn0);
            float p2 = __expf(sreg[j][2]-mn1), p3 = __expf(sreg[j][3]-mn1);
            rs0 += p0+p1; rs1 += p2+p3;
            O[j][0]*=al0; O[j][1]*=al0; O[j][2]*=al1; O[j][3]*=al1;
            int a0 = ((j*4 + 2*(q&1))*32 + w*8 + g)*4 + pbase;
            Qs[a0]       = tf32r(p0);   // (r,   c0)
            Qs[a0 + 128] = tf32r(p1);   // (r,   c1)  qa+1
            Qs[a0 + 1]   = tf32r(p2);   // (r+8, c0)
            Qs[a0 + 129] = tf32r(p3);   // (r+8, c1)
        }
        rs0 += __shfl_xor_sync(0xffffffffu, rs0, 1);
        rs0 += __shfl_xor_sync(0xffffffffu, rs0, 2);
        rs1 += __shfl_xor_sync(0xffffffffu, rs1, 1);
        rs1 += __shfl_xor_sync(0xffffffffu, rs1, 2);
        l0 += rs0; l1 += rs1;

        __syncwarp();   // P slots are warp-private

        // O += P V
        #pragma unroll
        for (int kk=0;kk<8;kk++){
            float4 pv = *(const float4*)&Qs[((kk*4+q)*32 + w*8 + g)*4];
            #pragma unroll
            for (int t=0;t<4;t++){
                float4 bv = *(const float4*)&V4[((kk*4+q)*32 + t*8 + g)*4];
                mma_tf32(O[2*t],   (const float*)&pv, &bv.x, O[2*t]);
                mma_tf32(O[2*t+1], (const float*)&pv, &bv.z, O[2*t+1]);
            }
        }
    }

    // write unnormalized partials + (m, l)
    const size_t rg0 = (size_t)b*T_ + q0 + w*16 + g;
    float* Po = g_po + (size_t)s*M_*H_ + rg0*H_;
    #pragma unroll
    for (int j=0;j<8;j++){
        *(float2*)&Po[j*8 + 2*q]        = make_float2(O[j][0], O[j][1]);
        *(float2*)&Po[8*H_ + j*8 + 2*q] = make_float2(O[j][2], O[j][3]);
    }
    if (q == 0){
        float* ml = g_ml + (size_t)s*M_*2;
        ml[rg0*2]     = m0r;  ml[rg0*2 + 1]     = l0;
        ml[(rg0+8)*2] = m1r;  ml[(rg0+8)*2 + 1] = l1;
    }
}

// ---------------------------------------------------------------------------
// Merge the two key-parity partials.
// ---------------------------------------------------------------------------
__global__ __launch_bounds__(256) void merge_kernel(float* __restrict__ out)
{
    const int idx = blockIdx.x*256 + threadIdx.x;
    const int row = idx >> 6;
    float ma = g_ml[row*2],        la = g_ml[row*2 + 1];
    float mb = g_ml[M_*2 + row*2], lb = g_ml[M_*2 + row*2 + 1];
    float M  = fmaxf(ma, mb);
    float ea = __expf(ma - M), eb = __expf(mb - M);
    float inv = 1.f / (la*ea + lb*eb);
    out[idx] = (g_po[idx]*ea + g_po[M_*H_ + idx]*eb) * inv;
}

extern "C" void kernel_launch(void* const* d_in, const int* in_sizes, int n_in,
                              void* d_out, int out_size)
{
    const float* x  = (const float*)d_in[0];
    const float* wq = (const float*)d_in[1];
    const float* wk = (const float*)d_in[2];
    const float* wv = (const float*)d_in[3];
    float* out = (float*)d_out;

    cudaFuncSetAttribute(qkv_kernel,
                         cudaFuncAttributeMaxDynamicSharedMemorySize, QKV_SMEM);
    cudaFuncSetAttribute(attn_kernel,
                         cudaFuncAttributeMaxDynamicSharedMemorySize, ATTN_SMEM);

    qkv_kernel<<<M_/128, 256, QKV_SMEM>>>(x, wq, wk, wv);
    dim3 grid(T_/64, B_, 2);
    attn_kernel<<<grid, 128, ATTN_SMEM>>>();
    merge_kernel<<<(M_*H_)/256, 256>>>(out);
}

// round 7
// speedup vs baseline: 2.3250x; 2.3250x over previous
#include <cuda_runtime.h>
#include <cstdint>

#define B_ 8
#define T_ 2048
#define C_ 1024
#define H_ 64
#define M_ (B_*T_)   // 16384

__device__ float g_q[M_*H_];
__device__ float g_k[M_*H_];
__device__ float g_v[M_*H_];
__device__ float g_po[2*M_*H_];
__device__ float g_ml[2*M_*2];

__device__ __forceinline__ float tf32r(float x){
    asm("cvt.rna.tf32.f32 %0, %0;" : "+f"(x));
    return x;
}
__device__ __forceinline__ float4 tf32r4(float4 v){
    v.x=tf32r(v.x); v.y=tf32r(v.y); v.z=tf32r(v.z); v.w=tf32r(v.w);
    return v;
}

__device__ __forceinline__ void mma_tf32(float* d, const float* a, const float* b, const float* c){
    asm volatile("mma.sync.aligned.m16n8k8.row.col.f32.tf32.tf32.f32 "
        "{%0,%1,%2,%3}, {%4,%5,%6,%7}, {%8,%9}, {%10,%11,%12,%13};"
        : "=f"(d[0]),"=f"(d[1]),"=f"(d[2]),"=f"(d[3])
        : "r"(__float_as_uint(a[0])),"r"(__float_as_uint(a[1])),
          "r"(__float_as_uint(a[2])),"r"(__float_as_uint(a[3])),
          "r"(__float_as_uint(b[0])),"r"(__float_as_uint(b[1])),
          "f"(c[0]),"f"(c[1]),"f"(c[2]),"f"(c[3]));
}

// ---------------------------------------------------------------------------
// Fused QKV projection (Round-3 version): BM=128, BN=192, BK=32, grid 128,
// 8 warps (4x2), warp tile 32x96, double-buffered register-staged pipeline.
// ---------------------------------------------------------------------------
#define AS_STRIDE 36   // ≡4 mod 32
#define BS_STRIDE 200  // ≡8 mod 32
#define QKV_SMEM ((2*128*AS_STRIDE + 2*32*BS_STRIDE)*4)

__global__ __launch_bounds__(256) void qkv_kernel(
    const float* __restrict__ x, const float* __restrict__ wq,
    const float* __restrict__ wk, const float* __restrict__ wv)
{
    extern __shared__ float sm[];
    float* Asm = sm;
    float* Bsm = sm + 2*128*AS_STRIDE;

    const int tid  = threadIdx.x;
    const int lane = tid & 31, warp = tid >> 5;
    const int wm = warp & 3, wn = warp >> 2;
    const int g = lane >> 2, q = lane & 3;
    const int m0 = blockIdx.x * 128;

    float acc[2][12][4];
    #pragma unroll
    for (int mi=0;mi<2;mi++)
        #pragma unroll
        for (int j=0;j<12;j++){acc[mi][j][0]=acc[mi][j][1]=acc[mi][j][2]=acc[mi][j][3]=0.f;}

    float4 xs[4], ws[3][2];

#define QKV_LOAD(K0) do { \
    _Pragma("unroll") \
    for (int it=0; it<4; it++){ \
        int i = tid + it*256; int r = i>>3, c4 = (i&7)*4; \
        xs[it] = *(const float4*)&x[(size_t)(m0+r)*C_ + (K0) + c4]; \
    } \
    _Pragma("unroll") \
    for (int it=0; it<2; it++){ \
        int i = tid + it*256; int r = i>>4, c4 = (i&15)*4; \
        int gi = ((K0)+r)*H_ + c4; \
        ws[0][it] = *(const float4*)&wq[gi]; \
        ws[1][it] = *(const float4*)&wk[gi]; \
        ws[2][it] = *(const float4*)&wv[gi]; \
    } } while(0)

#define QKV_STORE(BUF) do { \
    float* A  = Asm + (BUF)*128*AS_STRIDE; \
    float* Bb = Bsm + (BUF)*32*BS_STRIDE; \
    _Pragma("unroll") \
    for (int it=0; it<4; it++){ \
        int i = tid + it*256; int r = i>>3, c4 = (i&7)*4; \
        *(float4*)&A[r*AS_STRIDE + c4] = tf32r4(xs[it]); \
    } \
    _Pragma("unroll") \
    for (int it=0; it<2; it++){ \
        int i = tid + it*256; int r = i>>4, c4 = (i&15)*4; \
        *(float4*)&Bb[r*BS_STRIDE + c4]       = tf32r4(ws[0][it]); \
        *(float4*)&Bb[r*BS_STRIDE + 64 + c4]  = tf32r4(ws[1][it]); \
        *(float4*)&Bb[r*BS_STRIDE + 128 + c4] = tf32r4(ws[2][it]); \
    } } while(0)

#define QKV_COMPUTE(BUF) do { \
    const float* A  = Asm + (BUF)*128*AS_STRIDE; \
    const float* Bb = Bsm + (BUF)*32*BS_STRIDE; \
    _Pragma("unroll") \
    for (int kk=0;kk<4;kk++){ \
        float a[2][4]; \
        _Pragma("unroll") \
        for (int mi=0;mi<2;mi++){ \
            int base = (wm*32 + mi*16 + g)*AS_STRIDE + kk*8 + q; \
            a[mi][0]=A[base]; a[mi][1]=A[base + 8*AS_STRIDE]; \
            a[mi][2]=A[base+4]; a[mi][3]=A[base + 8*AS_STRIDE + 4]; \
        } \
        _Pragma("unroll") \
        for (int j=0;j<12;j++){ \
            float b[2]; int bc = wn*96 + j*8 + g; \
            b[0]=Bb[(kk*8+q)*BS_STRIDE + bc]; \
            b[1]=Bb[(kk*8+q+4)*BS_STRIDE + bc]; \
            mma_tf32(acc[0][j], a[0], b, acc[0][j]); \
            mma_tf32(acc[1][j], a[1], b, acc[1][j]); \
        } \
    } } while(0)

    QKV_LOAD(0);
    QKV_STORE(0);
    __syncthreads();

    #pragma unroll 1
    for (int c = 0; c < 32; c++){
        const int cur = c & 1;
        if (c < 31) QKV_LOAD((c+1) << 5);
        QKV_COMPUTE(cur);
        if (c < 31){
            QKV_STORE(cur ^ 1);
            __syncthreads();
        }
    }

    #pragma unroll
    for (int mi=0;mi<2;mi++){
        #pragma unroll
        for (int j=0;j<12;j++){
            int n  = wn*96 + j*8 + q*2;
            int r0 = m0 + wm*32 + mi*16 + g;
            float sc   = (n < 64) ? 0.03125f : 1.f;
            float* dst = (n < 64) ? g_q : ((n < 128) ? g_k : g_v);
            int nn     = (n < 64) ? n   : ((n < 128) ? n-64 : n-128);
            *(float2*)&dst[(size_t)r0*H_ + nn]     = make_float2(acc[mi][j][0]*sc, acc[mi][j][1]*sc);
            *(float2*)&dst[(size_t)(r0+8)*H_ + nn] = make_float2(acc[mi][j][2]*sc, acc[mi][j][3]*sc);
        }
    }
}

// ---------------------------------------------------------------------------
// Flash attention (Round-4 version): causal, tf32 mma, cross-CTA split-K by 2.
// ---------------------------------------------------------------------------
#define PS_STRIDE 68
#define KS_STRIDE 68
#define VS_STRIDE 72
#define ATTN_SMEM ((64*PS_STRIDE + 64*KS_STRIDE + 64*VS_STRIDE)*4)

__global__ __launch_bounds__(128) void attn_kernel()
{
    extern __shared__ float sm[];
    float* Qs = sm;
    float* Ks = sm + 64*PS_STRIDE;
    float* Vs = Ks + 64*KS_STRIDE;

    const int tid  = threadIdx.x;
    const int lane = tid & 31, w = tid >> 5;
    const int g = lane >> 2, q = lane & 3;
    const int qt = 31 - blockIdx.x;
    const int b  = blockIdx.y;
    const int s  = blockIdx.z;
    const int q0 = qt * 64;

    const float* Qg = g_q + ((size_t)b*T_ + q0)*H_;
    const float* Kg = g_k + (size_t)b*T_*H_;
    const float* Vg = g_v + (size_t)b*T_*H_;

    #pragma unroll
    for (int it=0; it<8; it++){
        int i = tid + it*128;
        int r = i>>4, c4 = (i&15)*4;
        *(float4*)&Qs[r*PS_STRIDE + c4] = tf32r4(*(const float4*)&Qg[(size_t)r*H_ + c4]);
    }
    __syncthreads();

    float qa[8][4];
    #pragma unroll
    for (int kk=0;kk<8;kk++){
        int base = (w*16+g)*PS_STRIDE + kk*8 + q;
        qa[kk][0]=Qs[base];
        qa[kk][1]=Qs[base + 8*PS_STRIDE];
        qa[kk][2]=Qs[base + 4];
        qa[kk][3]=Qs[base + 8*PS_STRIDE + 4];
    }
    __syncthreads();

    float O[8][4];
    #pragma unroll
    for (int j=0;j<8;j++){O[j][0]=O[j][1]=O[j][2]=O[j][3]=0.f;}
    float m0r=-1e30f, m1r=-1e30f, l0=0.f, l1=0.f;

    #pragma unroll 1
    for (int jt = s; jt <= qt; jt += 2){
        __syncthreads();
        const int k0 = jt*64;
        #pragma unroll
        for (int it=0; it<8; it++){
            int i = tid + it*128;
            int r = i>>4, c4 = (i&15)*4;
            *(float4*)&Ks[r*KS_STRIDE + c4] = tf32r4(*(const float4*)&Kg[(size_t)(k0+r)*H_ + c4]);
            *(float4*)&Vs[r*VS_STRIDE + c4] = tf32r4(*(const float4*)&Vg[(size_t)(k0+r)*H_ + c4]);
        }
        __syncthreads();

        float sreg[8][4];
        #pragma unroll
        for (int j=0;j<8;j++){sreg[j][0]=sreg[j][1]=sreg[j][2]=sreg[j][3]=0.f;}
        #pragma unroll
        for (int kk=0;kk<8;kk++){
            #pragma unroll
            for (int j=0;j<8;j++){
                float bb[2];
                int n = j*8 + g;
                bb[0]=Ks[n*KS_STRIDE + kk*8 + q];
                bb[1]=Ks[n*KS_STRIDE + kk*8 + q + 4];
                mma_tf32(sreg[j], qa[kk], bb, sreg[j]);
            }
        }

        if (jt == qt){
            #pragma unroll
            for (int j=0;j<8;j++){
                int c0 = j*8 + 2*q, c1 = c0+1;
                int r0l = w*16+g, r1l = r0l+8;
                if (c0 > r0l) sreg[j][0] = -1e30f;
                if (c1 > r0l) sreg[j][1] = -1e30f;
                if (c0 > r1l) sreg[j][2] = -1e30f;
                if (c1 > r1l) sreg[j][3] = -1e30f;
            }
        }

        float mx0=-1e30f, mx1=-1e30f;
        #pragma unroll
        for (int j=0;j<8;j++){
            mx0 = fmaxf(mx0, fmaxf(sreg[j][0], sreg[j][1]));
            mx1 = fmaxf(mx1, fmaxf(sreg[j][2], sreg[j][3]));
        }
        mx0 = fmaxf(mx0, __shfl_xor_sync(0xffffffffu, mx0, 1));
        mx0 = fmaxf(mx0, __shfl_xor_sync(0xffffffffu, mx0, 2));
        mx1 = fmaxf(mx1, __shfl_xor_sync(0xffffffffu, mx1, 1));
        mx1 = fmaxf(mx1, __shfl_xor_sync(0xffffffffu, mx1, 2));

        float mn0 = fmaxf(m0r, mx0), mn1 = fmaxf(m1r, mx1);
        float al0 = __expf(m0r - mn0), al1 = __expf(m1r - mn1);
        m0r = mn0; m1r = mn1;
        l0 *= al0; l1 *= al1;

        float rs0=0.f, rs1=0.f;
        #pragma unroll
        for (int j=0;j<8;j++){
            float p0 = __expf(sreg[j][0]-mn0), p1 = __expf(sreg[j][1]-mn0);
            float p2 = __expf(sreg[j][2]-mn1), p3 = __expf(sreg[j][3]-mn1);
            rs0 += p0+p1; rs1 += p2+p3;
            O[j][0]*=al0; O[j][1]*=al0; O[j][2]*=al1; O[j][3]*=al1;
            int rbase = (w*16+g)*PS_STRIDE + j*8 + 2*q;
            *(float2*)&Qs[rbase]               = make_float2(tf32r(p0), tf32r(p1));
            *(float2*)&Qs[rbase + 8*PS_STRIDE] = make_float2(tf32r(p2), tf32r(p3));
        }
        rs0 += __shfl_xor_sync(0xffffffffu, rs0, 1);
        rs0 += __shfl_xor_sync(0xffffffffu, rs0, 2);
        rs1 += __shfl_xor_sync(0xffffffffu, rs1, 1);
        rs1 += __shfl_xor_sync(0xffffffffu, rs1, 2);
        l0 += rs0; l1 += rs1;

        __syncwarp();

        #pragma unroll
        for (int kk=0;kk<8;kk++){
            float pa[4];
            int base = (w*16+g)*PS_STRIDE + kk*8 + q;
            pa[0]=Qs[base];
            pa[1]=Qs[base + 8*PS_STRIDE];
            pa[2]=Qs[base + 4];
            pa[3]=Qs[base + 8*PS_STRIDE + 4];
            #pragma unroll
            for (int j=0;j<8;j++){
                float bb[2];
                int hh = j*8 + g;
                bb[0]=Vs[(kk*8+q)*VS_STRIDE   + hh];
                bb[1]=Vs[(kk*8+q+4)*VS_STRIDE + hh];
                mma_tf32(O[j], pa, bb, O[j]);
            }
        }
    }

    const size_t rg0 = (size_t)b*T_ + q0 + w*16 + g;
    float* Po = g_po + (size_t)s*M_*H_ + rg0*H_;
    #pragma unroll
    for (int j=0;j<8;j++){
        *(float2*)&Po[j*8 + 2*q]        = make_float2(O[j][0], O[j][1]);
        *(float2*)&Po[8*H_ + j*8 + 2*q] = make_float2(O[j][2], O[j][3]);
    }
    if (q == 0){
        float* ml = g_ml + (size_t)s*M_*2;
        ml[rg0*2]     = m0r;  ml[rg0*2 + 1]     = l0;
        ml[(rg0+8)*2] = m1r;  ml[(rg0+8)*2 + 1] = l1;
    }
}

__global__ __launch_bounds__(256) void merge_kernel(float* __restrict__ out)
{
    const int idx = blockIdx.x*256 + threadIdx.x;
    const int row = idx >> 6;
    float ma = g_ml[row*2],        la = g_ml[row*2 + 1];
    float mb = g_ml[M_*2 + row*2], lb = g_ml[M_*2 + row*2 + 1];
    float M  = fmaxf(ma, mb);
    float ea = __expf(ma - M), eb = __expf(mb - M);
    float inv = 1.f / (la*ea + lb*eb);
    out[idx] = (g_po[idx]*ea + g_po[M_*H_ + idx]*eb) * inv;
}

extern "C" void kernel_launch(void* const* d_in, const int* in_sizes, int n_in,
                              void* d_out, int out_size)
{
    const float* x  = (const float*)d_in[0];
    const float* wq = (const float*)d_in[1];
    const float* wk = (const float*)d_in[2];
    const float* wv = (const float*)d_in[3];
    float* out = (float*)d_out;

    cudaFuncSetAttribute(qkv_kernel,
                         cudaFuncAttributeMaxDynamicSharedMemorySize, QKV_SMEM);
    cudaFuncSetAttribute(attn_kernel,
                         cudaFuncAttributeMaxDynamicSharedMemorySize, ATTN_SMEM);

    qkv_kernel<<<M_/128, 256, QKV_SMEM>>>(x, wq, wk, wv);
    dim3 grid(T_/64, B_, 2);
    attn_kernel<<<grid, 128, ATTN_SMEM>>>();
    merge_kernel<<<(M_*H_)/256, 256>>>(out);
}

// round 8
// speedup vs baseline: 2.5737x; 1.1069x over previous
#include <cuda_runtime.h>
#include <cstdint>

#define B_ 8
#define T_ 2048
#define C_ 1024
#define H_ 64
#define M_ (B_*T_)   // 16384
#define NSPLIT 4

__device__ float g_q[M_*H_];
__device__ float g_k[M_*H_];
__device__ float g_v[M_*H_];
__device__ float g_wt[1024*192];          // fused [k][q|k|v] weights, tf32, q-scaled
__device__ float g_po[NSPLIT*M_*H_];      // split partials
__device__ float g_ml[NSPLIT*M_*2];

__device__ __forceinline__ float tf32r(float x){
    asm("cvt.rna.tf32.f32 %0, %0;" : "+f"(x));
    return x;
}
__device__ __forceinline__ uint32_t su32(const void* p){
    uint32_t a;
    asm("{ .reg .u64 t; cvta.to.shared.u64 t, %1; cvt.u32.u64 %0, t; }" : "=r"(a) : "l"(p));
    return a;
}
__device__ __forceinline__ void cp16(uint32_t dst, const void* src){
    asm volatile("cp.async.cg.shared.global [%0], [%1], 16;" :: "r"(dst), "l"(src) : "memory");
}
#define CP_COMMIT() asm volatile("cp.async.commit_group;" ::: "memory")
#define CP_WAIT(n)  asm volatile("cp.async.wait_group %0;" :: "n"(n) : "memory")

__device__ __forceinline__ void mma_tf32(float* d, const float* a, const float* b, const float* c){
    asm volatile("mma.sync.aligned.m16n8k8.row.col.f32.tf32.tf32.f32 "
        "{%0,%1,%2,%3}, {%4,%5,%6,%7}, {%8,%9}, {%10,%11,%12,%13};"
        : "=f"(d[0]),"=f"(d[1]),"=f"(d[2]),"=f"(d[3])
        : "r"(__float_as_uint(a[0])),"r"(__float_as_uint(a[1])),
          "r"(__float_as_uint(a[2])),"r"(__float_as_uint(a[3])),
          "r"(__float_as_uint(b[0])),"r"(__float_as_uint(b[1])),
          "f"(c[0]),"f"(c[1]),"f"(c[2]),"f"(c[3]));
}

// ---------------------------------------------------------------------------
// Weight fuse+transpose-free convert: g_wt[k][n] (n: 0-63 q | 64-127 k | 128-191 v)
// tf32-rounded; C^-0.5 folded into the q columns.
// ---------------------------------------------------------------------------
__global__ __launch_bounds__(256) void wconv_kernel(
    const float* __restrict__ wq, const float* __restrict__ wk,
    const float* __restrict__ wv)
{
    int idx = blockIdx.x*256 + threadIdx.x;   // 0..196607
    int k = idx / 192, n = idx % 192;
    float v = (n < 64) ? wq[k*H_ + n] * 0.03125f
            : (n < 128) ? wk[k*H_ + n - 64]
                        : wv[k*H_ + n - 128];
    g_wt[idx] = tf32r(v);
}

// ---------------------------------------------------------------------------
// Fused QKV projection: BM=128, BN=192, BK=32, grid 128, 8 warps (4x2),
// 3-stage cp.async pipeline. A cvt'd at fragment read; B pre-converted (g_wt).
// Outputs written tf32-rounded (saves cvt in attention; identical math).
// ---------------------------------------------------------------------------
#define AS_STRIDE 36   // ≡4 mod 32
#define BS_STRIDE 200  // ≡8 mod 32
#define QKV_STAGE_A (128*AS_STRIDE)   // 4608 floats
#define QKV_STAGE_B (32*BS_STRIDE)    // 6400 floats
#define QKV_STAGES 3
#define QKV_SMEM (QKV_STAGES*(QKV_STAGE_A+QKV_STAGE_B)*4)   // 132096 B

__device__ __forceinline__ void qkv_load(int tid, int m0, int K0,
                                         const float* __restrict__ x,
                                         uint32_t Aa, uint32_t Ba)
{
    #pragma unroll
    for (int it=0; it<4; it++){
        int i = tid + it*256;            // 0..1023 ; 8 16B-chunks per 32-float row
        int r = i>>3, c = i&7;
        cp16(Aa + (uint32_t)(r*AS_STRIDE + c*4)*4u,
             &x[(size_t)(m0+r)*C_ + K0 + c*4]);
    }
    #pragma unroll
    for (int it=0; it<6; it++){
        int i = tid + it*256;            // 0..1535 ; 48 chunks per 192-float row
        int r = i/48, c = i%48;
        cp16(Ba + (uint32_t)(r*BS_STRIDE + c*4)*4u,
             &g_wt[(size_t)(K0+r)*192 + c*4]);
    }
    CP_COMMIT();
}

__global__ __launch_bounds__(256) void qkv_kernel(const float* __restrict__ x)
{
    extern __shared__ float sm[];
    float* Asm = sm;
    float* Bsm = sm + QKV_STAGES*QKV_STAGE_A;
    const uint32_t aA = su32(Asm), aB = su32(Bsm);

    const int tid  = threadIdx.x;
    const int lane = tid & 31, warp = tid >> 5;
    const int wm = warp & 3, wn = warp >> 2;
    const int g = lane >> 2, q = lane & 3;
    const int m0 = blockIdx.x * 128;

    float acc[2][12][4];
    #pragma unroll
    for (int mi=0;mi<2;mi++)
        #pragma unroll
        for (int j=0;j<12;j++){acc[mi][j][0]=acc[mi][j][1]=acc[mi][j][2]=acc[mi][j][3]=0.f;}

    qkv_load(tid, m0, 0,  x, aA,                      aB);
    qkv_load(tid, m0, 32, x, aA + QKV_STAGE_A*4u,     aB + QKV_STAGE_B*4u);

    #pragma unroll 1
    for (int c = 0; c < 32; c++){
        if (c < 31) { CP_WAIT(1); } else { CP_WAIT(0); }
        __syncthreads();
        if (c + 2 < 32){
            int st = (c+2) % QKV_STAGES;
            qkv_load(tid, m0, (c+2)*32, x,
                     aA + (uint32_t)st*QKV_STAGE_A*4u,
                     aB + (uint32_t)st*QKV_STAGE_B*4u);
        }
        const float* A  = Asm + (c % QKV_STAGES)*QKV_STAGE_A;
        const float* Bb = Bsm + (c % QKV_STAGES)*QKV_STAGE_B;
        #pragma unroll
        for (int kk=0;kk<4;kk++){
            float a[2][4];
            #pragma unroll
            for (int mi=0;mi<2;mi++){
                int base = (wm*32 + mi*16 + g)*AS_STRIDE + kk*8 + q;
                a[mi][0]=tf32r(A[base]);
                a[mi][1]=tf32r(A[base + 8*AS_STRIDE]);
                a[mi][2]=tf32r(A[base + 4]);
                a[mi][3]=tf32r(A[base + 8*AS_STRIDE + 4]);
            }
            #pragma unroll
            for (int j=0;j<12;j++){
                float b[2]; int bc = wn*96 + j*8 + g;
                b[0]=Bb[(kk*8+q)*BS_STRIDE + bc];
                b[1]=Bb[(kk*8+q+4)*BS_STRIDE + bc];
                mma_tf32(acc[0][j], a[0], b, acc[0][j]);
                mma_tf32(acc[1][j], a[1], b, acc[1][j]);
            }
        }
    }

    // epilogue: scatter tf32-rounded to g_q/g_k/g_v (scale pre-folded in g_wt)
    #pragma unroll
    for (int mi=0;mi<2;mi++){
        #pragma unroll
        for (int j=0;j<12;j++){
            int n  = wn*96 + j*8 + q*2;
            int r0 = m0 + wm*32 + mi*16 + g;
            float* dst = (n < 64) ? g_q : ((n < 128) ? g_k : g_v);
            int nn     = (n < 64) ? n   : ((n < 128) ? n-64 : n-128);
            *(float2*)&dst[(size_t)r0*H_ + nn] =
                make_float2(tf32r(acc[mi][j][0]), tf32r(acc[mi][j][1]));
            *(float2*)&dst[(size_t)(r0+8)*H_ + nn] =
                make_float2(tf32r(acc[mi][j][2]), tf32r(acc[mi][j][3]));
        }
    }
}

// ---------------------------------------------------------------------------
// Flash attention: causal, tf32 mma, cross-CTA split-K by 4, cp.async
// double-buffered K + single-buffered V (V load hides under S+softmax).
// Inputs pre-tf32-rounded/pre-scaled by qkv.
// smem: Q/P 4352f | K0 4352f | K1 4352f | V 4608f = 70656 B  -> 3 CTAs/SM
// ---------------------------------------------------------------------------
#define PS_STRIDE 68
#define KS_STRIDE 68
#define VS_STRIDE 72
#define ATTN_SMEM ((4352 + 2*4352 + 4608)*4)

__device__ __forceinline__ void attn_ldtile(int tid, const float* __restrict__ src,
                                            uint32_t dst, int stride)
{
    #pragma unroll
    for (int it=0; it<8; it++){
        int i = tid + it*128;            // 0..1023 ; 16 chunks per 64-float row
        int r = i>>4, c = i&15;
        cp16(dst + (uint32_t)(r*stride + c*4)*4u, &src[(size_t)r*H_ + c*4]);
    }
    CP_COMMIT();
}

__global__ __launch_bounds__(128, 3) void attn_kernel()
{
    extern __shared__ float sm[];
    float* Qs = sm;                       // Q staging, then P
    float* Kb[2] = { sm + 4352, sm + 8704 };
    float* Vs = sm + 13056;
    const uint32_t aK0 = su32(Kb[0]), aK1 = su32(Kb[1]), aV = su32(Vs);

    const int tid  = threadIdx.x;
    const int lane = tid & 31, w = tid >> 5;
    const int g = lane >> 2, q = lane & 3;
    const int qt = 31 - blockIdx.x;       // heavy blocks first
    const int b  = blockIdx.y;
    const int s  = blockIdx.z;            // split id 0..3
    const int q0 = qt * 64;

    const float* Qg = g_q + ((size_t)b*T_ + q0)*H_;
    const float* Kg = g_k + (size_t)b*T_*H_;
    const float* Vg = g_v + (size_t)b*T_*H_;

    const int ntiles = (qt >= s) ? ((qt - s) >> 2) + 1 : 0;

    // stage Q (already tf32+scaled)
    #pragma unroll
    for (int it=0; it<8; it++){
        int i = tid + it*128;
        int r = i>>4, c4 = (i&15)*4;
        *(float4*)&Qs[r*PS_STRIDE + c4] = *(const float4*)&Qg[(size_t)r*H_ + c4];
    }
    __syncthreads();

    float qa[8][4];
    #pragma unroll
    for (int kk=0;kk<8;kk++){
        int base = (w*16+g)*PS_STRIDE + kk*8 + q;
        qa[kk][0]=Qs[base];
        qa[kk][1]=Qs[base + 8*PS_STRIDE];
        qa[kk][2]=Qs[base + 4];
        qa[kk][3]=Qs[base + 8*PS_STRIDE + 4];
    }
    __syncthreads();   // Qs now reusable as P

    float O[8][4];
    #pragma unroll
    for (int j=0;j<8;j++){O[j][0]=O[j][1]=O[j][2]=O[j][3]=0.f;}
    float m0r=-1e30f, m1r=-1e30f, l0=0.f, l1=0.f;

    if (ntiles > 0)
        attn_ldtile(tid, Kg + (size_t)s*64*H_, aK0, KS_STRIDE);

    #pragma unroll 1
    for (int t = 0; t < ntiles; t++){
        const int jt = s + t*NSPLIT;
        const int k0 = jt*64;

        CP_WAIT(0);            // K(t) ready
        __syncthreads();       // all warps done with prev tile's K/V/P

        // V(t) first (older group), then K(t+1)
        attn_ldtile(tid, Vg + (size_t)k0*H_, aV, VS_STRIDE);
        if (t + 1 < ntiles)
            attn_ldtile(tid, Kg + (size_t)(k0 + NSPLIT*64)*H_, (t&1)?aK0:aK1, KS_STRIDE);

        const float* Ks = Kb[t & 1];

        // S = Q K^T (scale pre-folded)
        float sreg[8][4];
        #pragma unroll
        for (int j=0;j<8;j++){sreg[j][0]=sreg[j][1]=sreg[j][2]=sreg[j][3]=0.f;}
        #pragma unroll
        for (int kk=0;kk<8;kk++){
            #pragma unroll
            for (int j=0;j<8;j++){
                float bb[2];
                int n = j*8 + g;
                bb[0]=Ks[n*KS_STRIDE + kk*8 + q];
                bb[1]=Ks[n*KS_STRIDE + kk*8 + q + 4];
                mma_tf32(sreg[j], qa[kk], bb, sreg[j]);
            }
        }

        if (jt == qt){   // diagonal tile -> causal mask (tile-aligned)
            #pragma unroll
            for (int j=0;j<8;j++){
                int c0 = j*8 + 2*q, c1 = c0+1;
                int r0l = w*16+g, r1l = r0l+8;
                if (c0 > r0l) sreg[j][0] = -1e30f;
                if (c1 > r0l) sreg[j][1] = -1e30f;
                if (c0 > r1l) sreg[j][2] = -1e30f;
                if (c1 > r1l) sreg[j][3] = -1e30f;
            }
        }

        // online softmax (registers + quad shuffles)
        float mx0=-1e30f, mx1=-1e30f;
        #pragma unroll
        for (int j=0;j<8;j++){
            mx0 = fmaxf(mx0, fmaxf(sreg[j][0], sreg[j][1]));
            mx1 = fmaxf(mx1, fmaxf(sreg[j][2], sreg[j][3]));
        }
        mx0 = fmaxf(mx0, __shfl_xor_sync(0xffffffffu, mx0, 1));
        mx0 = fmaxf(mx0, __shfl_xor_sync(0xffffffffu, mx0, 2));
        mx1 = fmaxf(mx1, __shfl_xor_sync(0xffffffffu, mx1, 1));
        mx1 = fmaxf(mx1, __shfl_xor_sync(0xffffffffu, mx1, 2));

        float mn0 = fmaxf(m0r, mx0), mn1 = fmaxf(m1r, mx1);
        float al0 = __expf(m0r - mn0), al1 = __expf(m1r - mn1);
        m0r = mn0; m1r = mn1;
        l0 *= al0; l1 *= al1;

        float rs0=0.f, rs1=0.f;
        #pragma unroll
        for (int j=0;j<8;j++){
            float p0 = __expf(sreg[j][0]-mn0), p1 = __expf(sreg[j][1]-mn0);
            float p2 = __expf(sreg[j][2]-mn1), p3 = __expf(sreg[j][3]-mn1);
            rs0 += p0+p1; rs1 += p2+p3;
            O[j][0]*=al0; O[j][1]*=al0; O[j][2]*=al1; O[j][3]*=al1;
            int rbase = (w*16+g)*PS_STRIDE + j*8 + 2*q;
            *(float2*)&Qs[rbase]               = make_float2(tf32r(p0), tf32r(p1));
            *(float2*)&Qs[rbase + 8*PS_STRIDE] = make_float2(tf32r(p2), tf32r(p3));
        }
        rs0 += __shfl_xor_sync(0xffffffffu, rs0, 1);
        rs0 += __shfl_xor_sync(0xffffffffu, rs0, 2);
        rs1 += __shfl_xor_sync(0xffffffffu, rs1, 1);
        rs1 += __shfl_xor_sync(0xffffffffu, rs1, 2);
        l0 += rs0; l1 += rs1;

        // V(t) must be complete and visible (K(t+1) may stay in flight)
        if (t + 1 < ntiles) { CP_WAIT(1); } else { CP_WAIT(0); }
        __syncthreads();

        // O += P V
        #pragma unroll
        for (int kk=0;kk<8;kk++){
            float pa[4];
            int base = (w*16+g)*PS_STRIDE + kk*8 + q;
            pa[0]=Qs[base];
            pa[1]=Qs[base + 8*PS_STRIDE];
            pa[2]=Qs[base + 4];
            pa[3]=Qs[base + 8*PS_STRIDE + 4];
            #pragma unroll
            for (int j=0;j<8;j++){
                float bb[2];
                int hh = j*8 + g;
                bb[0]=Vs[(kk*8+q)*VS_STRIDE   + hh];
                bb[1]=Vs[(kk*8+q+4)*VS_STRIDE + hh];
                mma_tf32(O[j], pa, bb, O[j]);
            }
        }
    }

    // write unnormalized partials + (m, l)
    const size_t rg0 = (size_t)b*T_ + q0 + w*16 + g;
    float* Po = g_po + (size_t)s*M_*H_ + rg0*H_;
    #pragma unroll
    for (int j=0;j<8;j++){
        *(float2*)&Po[j*8 + 2*q]        = make_float2(O[j][0], O[j][1]);
        *(float2*)&Po[8*H_ + j*8 + 2*q] = make_float2(O[j][2], O[j][3]);
    }
    if (q == 0){
        float* ml = g_ml + (size_t)s*M_*2;
        ml[rg0*2]     = m0r;  ml[rg0*2 + 1]     = l0;
        ml[(rg0+8)*2] = m1r;  ml[(rg0+8)*2 + 1] = l1;
    }
}

// ---------------------------------------------------------------------------
// Merge the NSPLIT partials.
// ---------------------------------------------------------------------------
__global__ __launch_bounds__(256) void merge_kernel(float* __restrict__ out)
{
    const int idx = blockIdx.x*256 + threadIdx.x;
    const int row = idx >> 6;
    float m[NSPLIT], l[NSPLIT], M = -1e30f;
    #pragma unroll
    for (int s=0;s<NSPLIT;s++){
        m[s] = g_ml[(size_t)s*M_*2 + row*2];
        l[s] = g_ml[(size_t)s*M_*2 + row*2 + 1];
        M = fmaxf(M, m[s]);
    }
    float num = 0.f, den = 0.f;
    #pragma unroll
    for (int s=0;s<NSPLIT;s++){
        float e = __expf(m[s] - M);
        den += l[s]*e;
        num += g_po[(size_t)s*M_*H_ + idx]*e;
    }
    out[idx] = num/den;
}

extern "C" void kernel_launch(void* const* d_in, const int* in_sizes, int n_in,
                              void* d_out, int out_size)
{
    const float* x  = (const float*)d_in[0];
    const float* wq = (const float*)d_in[1];
    const float* wk = (const float*)d_in[2];
    const float* wv = (const float*)d_in[3];
    float* out = (float*)d_out;

    cudaFuncSetAttribute(qkv_kernel,
                         cudaFuncAttributeMaxDynamicSharedMemorySize, QKV_SMEM);
    cudaFuncSetAttribute(attn_kernel,
                         cudaFuncAttributeMaxDynamicSharedMemorySize, ATTN_SMEM);

    wconv_kernel<<<768, 256>>>(wq, wk, wv);
    qkv_kernel<<<M_/128, 256, QKV_SMEM>>>(x);
    dim3 grid(T_/64, B_, NSPLIT);
    attn_kernel<<<grid, 128, ATTN_SMEM>>>();
    merge_kernel<<<(M_*H_)/256, 256>>>(out);
}

// round 9
// speedup vs baseline: 2.6789x; 1.0409x over previous
#include <cuda_runtime.h>
#include <cstdint>

#define B_ 8
#define T_ 2048
#define C_ 1024
#define H_ 64
#define M_ (B_*T_)   // 16384
#define NSPLIT 4

__device__ float g_q[M_*H_];
__device__ float g_k[M_*H_];
__device__ float g_v[M_*H_];
__device__ float g_wt[1024*192];          // fused [k][q|k|v] weights, tf32, q-scaled(log2e)
__device__ float g_po[NSPLIT*M_*H_];
__device__ float g_ml[NSPLIT*M_*2];

__device__ __forceinline__ float tf32r(float x){
    asm("cvt.rna.tf32.f32 %0, %0;" : "+f"(x));
    return x;
}
__device__ __forceinline__ uint32_t su32(const void* p){
    uint32_t a;
    asm("{ .reg .u64 t; cvta.to.shared.u64 t, %1; cvt.u32.u64 %0, t; }" : "=r"(a) : "l"(p));
    return a;
}
__device__ __forceinline__ void cp16(uint32_t dst, const void* src){
    asm volatile("cp.async.cg.shared.global [%0], [%1], 16;" :: "r"(dst), "l"(src) : "memory");
}
#define CP_COMMIT() asm volatile("cp.async.commit_group;" ::: "memory")
#define CP_WAIT(n)  asm volatile("cp.async.wait_group %0;" :: "n"(n) : "memory")

__device__ __forceinline__ void mma_tf32(float* d, const float* a, const float* b, const float* c){
    asm volatile("mma.sync.aligned.m16n8k8.row.col.f32.tf32.tf32.f32 "
        "{%0,%1,%2,%3}, {%4,%5,%6,%7}, {%8,%9}, {%10,%11,%12,%13};"
        : "=f"(d[0]),"=f"(d[1]),"=f"(d[2]),"=f"(d[3])
        : "r"(__float_as_uint(a[0])),"r"(__float_as_uint(a[1])),
          "r"(__float_as_uint(a[2])),"r"(__float_as_uint(a[3])),
          "r"(__float_as_uint(b[0])),"r"(__float_as_uint(b[1])),
          "f"(c[0]),"f"(c[1]),"f"(c[2]),"f"(c[3]));
}

// ---------------------------------------------------------------------------
// Weight fuse/convert: g_wt[k][n]; n: 0-63 q | 64-127 k | 128-191 v.
// tf32-rounded; (C^-0.5 * log2e) folded into q columns (exp2 softmax domain).
// ---------------------------------------------------------------------------
__global__ __launch_bounds__(192) void wconv_kernel(
    const float* __restrict__ wq, const float* __restrict__ wk,
    const float* __restrict__ wv)
{
    const int k = blockIdx.x;        // 0..1023
    const int n = threadIdx.x;       // 0..191
    const float QSCALE = 0.03125f * 1.44269504f;
    float v = (n < 64) ? wq[k*H_ + n] * QSCALE
            : (n < 128) ? wk[k*H_ + n - 64]
                        : wv[k*H_ + n - 128];
    g_wt[k*192 + n] = tf32r(v);
}

// ---------------------------------------------------------------------------
// Fused QKV projection: BM=128, BN=192, BK=32, grid 128, 8 warps (4x2),
// 4-stage cp.async pipeline.
// ---------------------------------------------------------------------------
#define AS_STRIDE 36   // ≡4 mod 32
#define BS_STRIDE 200  // ≡8 mod 32
#define QKV_STAGE_A (128*AS_STRIDE)   // 4608 floats
#define QKV_STAGE_B (32*BS_STRIDE)    // 6400 floats
#define QKV_STAGES 4
#define QKV_SMEM (QKV_STAGES*(QKV_STAGE_A+QKV_STAGE_B)*4)   // 176128 B

__device__ __forceinline__ void qkv_load(int tid, int m0, int K0,
                                         const float* __restrict__ x,
                                         uint32_t Aa, uint32_t Ba)
{
    #pragma unroll
    for (int it=0; it<4; it++){
        int i = tid + it*256;
        int r = i>>3, c = i&7;
        cp16(Aa + (uint32_t)(r*AS_STRIDE + c*4)*4u,
             &x[(size_t)(m0+r)*C_ + K0 + c*4]);
    }
    #pragma unroll
    for (int it=0; it<6; it++){
        int i = tid + it*256;
        int r = i/48, c = i%48;
        cp16(Ba + (uint32_t)(r*BS_STRIDE + c*4)*4u,
             &g_wt[(size_t)(K0+r)*192 + c*4]);
    }
    CP_COMMIT();
}

__global__ __launch_bounds__(256) void qkv_kernel(const float* __restrict__ x)
{
    extern __shared__ float sm[];
    float* Asm = sm;
    float* Bsm = sm + QKV_STAGES*QKV_STAGE_A;
    const uint32_t aA = su32(Asm), aB = su32(Bsm);

    const int tid  = threadIdx.x;
    const int lane = tid & 31, warp = tid >> 5;
    const int wm = warp & 3, wn = warp >> 2;
    const int g = lane >> 2, q = lane & 3;
    const int m0 = blockIdx.x * 128;

    float acc[2][12][4];
    #pragma unroll
    for (int mi=0;mi<2;mi++)
        #pragma unroll
        for (int j=0;j<12;j++){acc[mi][j][0]=acc[mi][j][1]=acc[mi][j][2]=acc[mi][j][3]=0.f;}

    qkv_load(tid, m0, 0,  x, aA,                    aB);
    qkv_load(tid, m0, 32, x, aA + QKV_STAGE_A*4u,   aB + QKV_STAGE_B*4u);
    qkv_load(tid, m0, 64, x, aA + 2*QKV_STAGE_A*4u, aB + 2*QKV_STAGE_B*4u);

    #pragma unroll 1
    for (int c = 0; c < 32; c++){
        if (c < 30)      { CP_WAIT(2); }
        else if (c == 30){ CP_WAIT(1); }
        else             { CP_WAIT(0); }
        __syncthreads();
        if (c + 3 < 32){
            int st = (c+3) & 3;
            qkv_load(tid, m0, (c+3)*32, x,
                     aA + (uint32_t)st*QKV_STAGE_A*4u,
                     aB + (uint32_t)st*QKV_STAGE_B*4u);
        }
        const float* A  = Asm + (c & 3)*QKV_STAGE_A;
        const float* Bb = Bsm + (c & 3)*QKV_STAGE_B;
        #pragma unroll
        for (int kk=0;kk<4;kk++){
            float a[2][4];
            #pragma unroll
            for (int mi=0;mi<2;mi++){
                int base = (wm*32 + mi*16 + g)*AS_STRIDE + kk*8 + q;
                a[mi][0]=tf32r(A[base]);
                a[mi][1]=tf32r(A[base + 8*AS_STRIDE]);
                a[mi][2]=tf32r(A[base + 4]);
                a[mi][3]=tf32r(A[base + 8*AS_STRIDE + 4]);
            }
            #pragma unroll
            for (int j=0;j<12;j++){
                float b[2]; int bc = wn*96 + j*8 + g;
                b[0]=Bb[(kk*8+q)*BS_STRIDE + bc];
                b[1]=Bb[(kk*8+q+4)*BS_STRIDE + bc];
                mma_tf32(acc[0][j], a[0], b, acc[0][j]);
                mma_tf32(acc[1][j], a[1], b, acc[1][j]);
            }
        }
    }

    #pragma unroll
    for (int mi=0;mi<2;mi++){
        #pragma unroll
        for (int j=0;j<12;j++){
            int n  = wn*96 + j*8 + q*2;
            int r0 = m0 + wm*32 + mi*16 + g;
            float* dst = (n < 64) ? g_q : ((n < 128) ? g_k : g_v);
            int nn     = (n < 64) ? n   : ((n < 128) ? n-64 : n-128);
            *(float2*)&dst[(size_t)r0*H_ + nn] =
                make_float2(tf32r(acc[mi][j][0]), tf32r(acc[mi][j][1]));
            *(float2*)&dst[(size_t)(r0+8)*H_ + nn] =
                make_float2(tf32r(acc[mi][j][2]), tf32r(acc[mi][j][3]));
        }
    }
}

// ---------------------------------------------------------------------------
// Flash attention: causal, tf32 mma, cross-CTA split-K by 4, cp.async K
// double-buffered + V single-buffered. Softmax in exp2 domain (scale folded).
// ---------------------------------------------------------------------------
#define PS_STRIDE 68
#define KS_STRIDE 68
#define VS_STRIDE 72
#define ATTN_SMEM ((4352 + 2*4352 + 4608)*4)

__device__ __forceinline__ void attn_ldtile(int tid, const float* __restrict__ src,
                                            uint32_t dst, int stride)
{
    #pragma unroll
    for (int it=0; it<8; it++){
        int i = tid + it*128;
        int r = i>>4, c = i&15;
        cp16(dst + (uint32_t)(r*stride + c*4)*4u, &src[(size_t)r*H_ + c*4]);
    }
    CP_COMMIT();
}

__global__ __launch_bounds__(128, 3) void attn_kernel()
{
    extern __shared__ float sm[];
    float* Qs = sm;
    float* Kb[2] = { sm + 4352, sm + 8704 };
    float* Vs = sm + 13056;
    const uint32_t aK0 = su32(Kb[0]), aK1 = su32(Kb[1]), aV = su32(Vs);

    const int tid  = threadIdx.x;
    const int lane = tid & 31, w = tid >> 5;
    const int g = lane >> 2, q = lane & 3;
    const int qt = 31 - blockIdx.x;
    const int b  = blockIdx.y;
    const int s  = blockIdx.z;
    const int q0 = qt * 64;

    const float* Qg = g_q + ((size_t)b*T_ + q0)*H_;
    const float* Kg = g_k + (size_t)b*T_*H_;
    const float* Vg = g_v + (size_t)b*T_*H_;

    const int ntiles = (qt >= s) ? ((qt - s) >> 2) + 1 : 0;

    #pragma unroll
    for (int it=0; it<8; it++){
        int i = tid + it*128;
        int r = i>>4, c4 = (i&15)*4;
        *(float4*)&Qs[r*PS_STRIDE + c4] = *(const float4*)&Qg[(size_t)r*H_ + c4];
    }
    __syncthreads();

    float qa[8][4];
    #pragma unroll
    for (int kk=0;kk<8;kk++){
        int base = (w*16+g)*PS_STRIDE + kk*8 + q;
        qa[kk][0]=Qs[base];
        qa[kk][1]=Qs[base + 8*PS_STRIDE];
        qa[kk][2]=Qs[base + 4];
        qa[kk][3]=Qs[base + 8*PS_STRIDE + 4];
    }
    __syncthreads();

    float O[8][4];
    #pragma unroll
    for (int j=0;j<8;j++){O[j][0]=O[j][1]=O[j][2]=O[j][3]=0.f;}
    float m0r=-1e30f, m1r=-1e30f, l0=0.f, l1=0.f;

    if (ntiles > 0)
        attn_ldtile(tid, Kg + (size_t)s*64*H_, aK0, KS_STRIDE);

    #pragma unroll 1
    for (int t = 0; t < ntiles; t++){
        const int jt = s + t*NSPLIT;
        const int k0 = jt*64;

        CP_WAIT(0);
        __syncthreads();

        attn_ldtile(tid, Vg + (size_t)k0*H_, aV, VS_STRIDE);
        if (t + 1 < ntiles)
            attn_ldtile(tid, Kg + (size_t)(k0 + NSPLIT*64)*H_, (t&1)?aK0:aK1, KS_STRIDE);

        const float* Ks = Kb[t & 1];

        // S = Q K^T (log2e*scale pre-folded into q)
        float sreg[8][4];
        #pragma unroll
        for (int j=0;j<8;j++){sreg[j][0]=sreg[j][1]=sreg[j][2]=sreg[j][3]=0.f;}
        #pragma unroll
        for (int kk=0;kk<8;kk++){
            #pragma unroll
            for (int j=0;j<8;j++){
                float bb[2];
                int n = j*8 + g;
                bb[0]=Ks[n*KS_STRIDE + kk*8 + q];
                bb[1]=Ks[n*KS_STRIDE + kk*8 + q + 4];
                mma_tf32(sreg[j], qa[kk], bb, sreg[j]);
            }
        }

        if (jt == qt){
            #pragma unroll
            for (int j=0;j<8;j++){
                int c0 = j*8 + 2*q, c1 = c0+1;
                int r0l = w*16+g, r1l = r0l+8;
                if (c0 > r0l) sreg[j][0] = -1e30f;
                if (c1 > r0l) sreg[j][1] = -1e30f;
                if (c0 > r1l) sreg[j][2] = -1e30f;
                if (c1 > r1l) sreg[j][3] = -1e30f;
            }
        }

        // online softmax, exp2 domain
        float mx0=-1e30f, mx1=-1e30f;
        #pragma unroll
        for (int j=0;j<8;j++){
            mx0 = fmaxf(mx0, fmaxf(sreg[j][0], sreg[j][1]));
            mx1 = fmaxf(mx1, fmaxf(sreg[j][2], sreg[j][3]));
        }
        mx0 = fmaxf(mx0, __shfl_xor_sync(0xffffffffu, mx0, 1));
        mx0 = fmaxf(mx0, __shfl_xor_sync(0xffffffffu, mx0, 2));
        mx1 = fmaxf(mx1, __shfl_xor_sync(0xffffffffu, mx1, 1));
        mx1 = fmaxf(mx1, __shfl_xor_sync(0xffffffffu, mx1, 2));

        float mn0 = fmaxf(m0r, mx0), mn1 = fmaxf(m1r, mx1);
        float al0 = exp2f(m0r - mn0), al1 = exp2f(m1r - mn1);
        m0r = mn0; m1r = mn1;
        l0 *= al0; l1 *= al1;

        float rs0=0.f, rs1=0.f;
        #pragma unroll
        for (int j=0;j<8;j++){
            float p0 = exp2f(sreg[j][0]-mn0), p1 = exp2f(sreg[j][1]-mn0);
            float p2 = exp2f(sreg[j][2]-mn1), p3 = exp2f(sreg[j][3]-mn1);
            rs0 += p0+p1; rs1 += p2+p3;
            O[j][0]*=al0; O[j][1]*=al0; O[j][2]*=al1; O[j][3]*=al1;
            int rbase = (w*16+g)*PS_STRIDE + j*8 + 2*q;
            *(float2*)&Qs[rbase]               = make_float2(tf32r(p0), tf32r(p1));
            *(float2*)&Qs[rbase + 8*PS_STRIDE] = make_float2(tf32r(p2), tf32r(p3));
        }
        rs0 += __shfl_xor_sync(0xffffffffu, rs0, 1);
        rs0 += __shfl_xor_sync(0xffffffffu, rs0, 2);
        rs1 += __shfl_xor_sync(0xffffffffu, rs1, 1);
        rs1 += __shfl_xor_sync(0xffffffffu, rs1, 2);
        l0 += rs0; l1 += rs1;

        if (t + 1 < ntiles) { CP_WAIT(1); } else { CP_WAIT(0); }
        __syncthreads();

        // O += P V
        #pragma unroll
        for (int kk=0;kk<8;kk++){
            float pa[4];
            int base = (w*16+g)*PS_STRIDE + kk*8 + q;
            pa[0]=Qs[base];
            pa[1]=Qs[base + 8*PS_STRIDE];
            pa[2]=Qs[base + 4];
            pa[3]=Qs[base + 8*PS_STRIDE + 4];
            #pragma unroll
            for (int j=0;j<8;j++){
                float bb[2];
                int hh = j*8 + g;
                bb[0]=Vs[(kk*8+q)*VS_STRIDE   + hh];
                bb[1]=Vs[(kk*8+q+4)*VS_STRIDE + hh];
                mma_tf32(O[j], pa, bb, O[j]);
            }
        }
    }

    const size_t rg0 = (size_t)b*T_ + q0 + w*16 + g;
    float* Po = g_po + (size_t)s*M_*H_ + rg0*H_;
    #pragma unroll
    for (int j=0;j<8;j++){
        *(float2*)&Po[j*8 + 2*q]        = make_float2(O[j][0], O[j][1]);
        *(float2*)&Po[8*H_ + j*8 + 2*q] = make_float2(O[j][2], O[j][3]);
    }
    if (q == 0){
        float* ml = g_ml + (size_t)s*M_*2;
        ml[rg0*2]     = m0r;  ml[rg0*2 + 1]     = l0;
        ml[(rg0+8)*2] = m1r;  ml[(rg0+8)*2 + 1] = l1;
    }
}

// ---------------------------------------------------------------------------
// Merge the NSPLIT partials. float4 per thread (exp2 domain).
// ---------------------------------------------------------------------------
__global__ __launch_bounds__(256) void merge_kernel(float* __restrict__ out)
{
    const int idx4 = blockIdx.x*256 + threadIdx.x;   // [0, M_*H_/4)
    const int row  = idx4 >> 4;
    float m[NSPLIT], l[NSPLIT], M = -1e30f;
    #pragma unroll
    for (int s=0;s<NSPLIT;s++){
        float2 ml = *(const float2*)&g_ml[(size_t)s*M_*2 + row*2];
        m[s] = ml.x; l[s] = ml.y;
        M = fmaxf(M, m[s]);
    }
    float4 num = make_float4(0.f,0.f,0.f,0.f);
    float den = 0.f;
    #pragma unroll
    for (int s=0;s<NSPLIT;s++){
        float e = exp2f(m[s] - M);
        den += l[s]*e;
        float4 po = *(const float4*)&g_po[(size_t)s*M_*H_ + idx4*4];
        num.x += po.x*e; num.y += po.y*e; num.z += po.z*e; num.w += po.w*e;
    }
    float inv = 1.f/den;
    *(float4*)&out[idx4*4] = make_float4(num.x*inv, num.y*inv, num.z*inv, num.w*inv);
}

extern "C" void kernel_launch(void* const* d_in, const int* in_sizes, int n_in,
                              void* d_out, int out_size)
{
    const float* x  = (const float*)d_in[0];
    const float* wq = (const float*)d_in[1];
    const float* wk = (const float*)d_in[2];
    const float* wv = (const float*)d_in[3];
    float* out = (float*)d_out;

    cudaFuncSetAttribute(qkv_kernel,
                         cudaFuncAttributeMaxDynamicSharedMemorySize, QKV_SMEM);
    cudaFuncSetAttribute(attn_kernel,
                         cudaFuncAttributeMaxDynamicSharedMemorySize, ATTN_SMEM);

    wconv_kernel<<<1024, 192>>>(wq, wk, wv);
    qkv_kernel<<<M_/128, 256, QKV_SMEM>>>(x);
    dim3 grid(T_/64, B_, NSPLIT);
    attn_kernel<<<grid, 128, ATTN_SMEM>>>();
    merge_kernel<<<(M_*H_)/1024, 256>>>(out);
}

// round 10
// speedup vs baseline: 2.7161x; 1.0139x over previous
#include <cuda_runtime.h>
#include <cstdint>

#define B_ 8
#define T_ 2048
#define C_ 1024
#define H_ 64
#define M_ (B_*T_)   // 16384
#define NSPLIT 4

__device__ float g_q[M_*H_];
__device__ float g_k[M_*H_];
__device__ float g_v[M_*H_];
__device__ float g_wt[1024*192];
__device__ float g_po[NSPLIT*M_*H_];
__device__ float g_ml[NSPLIT*M_*2];

__device__ __forceinline__ float tf32r(float x){
    asm("cvt.rna.tf32.f32 %0, %0;" : "+f"(x));
    return x;
}
__device__ __forceinline__ uint32_t su32(const void* p){
    uint32_t a;
    asm("{ .reg .u64 t; cvta.to.shared.u64 t, %1; cvt.u32.u64 %0, t; }" : "=r"(a) : "l"(p));
    return a;
}
__device__ __forceinline__ void cp16(uint32_t dst, const void* src){
    asm volatile("cp.async.cg.shared.global [%0], [%1], 16;" :: "r"(dst), "l"(src) : "memory");
}
#define CP_COMMIT() asm volatile("cp.async.commit_group;" ::: "memory")
#define CP_WAIT(n)  asm volatile("cp.async.wait_group %0;" :: "n"(n) : "memory")

__device__ __forceinline__ void mma_tf32(float* d, const float* a, const float* b, const float* c){
    asm volatile("mma.sync.aligned.m16n8k8.row.col.f32.tf32.tf32.f32 "
        "{%0,%1,%2,%3}, {%4,%5,%6,%7}, {%8,%9}, {%10,%11,%12,%13};"
        : "=f"(d[0]),"=f"(d[1]),"=f"(d[2]),"=f"(d[3])
        : "r"(__float_as_uint(a[0])),"r"(__float_as_uint(a[1])),
          "r"(__float_as_uint(a[2])),"r"(__float_as_uint(a[3])),
          "r"(__float_as_uint(b[0])),"r"(__float_as_uint(b[1])),
          "f"(c[0]),"f"(c[1]),"f"(c[2]),"f"(c[3]));
}

// ---------------------------------------------------------------------------
// Weight fuse/convert (q-scale * log2e folded).
// ---------------------------------------------------------------------------
__global__ __launch_bounds__(192) void wconv_kernel(
    const float* __restrict__ wq, const float* __restrict__ wk,
    const float* __restrict__ wv)
{
    const int k = blockIdx.x;
    const int n = threadIdx.x;
    const float QSCALE = 0.03125f * 1.44269504f;
    float v = (n < 64) ? wq[k*H_ + n] * QSCALE
            : (n < 128) ? wk[k*H_ + n - 64]
                        : wv[k*H_ + n - 128];
    g_wt[k*192 + n] = tf32r(v);
}

// ---------------------------------------------------------------------------
// Fused QKV projection (Round-9 version, 4-stage cp.async).
// ---------------------------------------------------------------------------
#define AS_STRIDE 36
#define BS_STRIDE 200
#define QKV_STAGE_A (128*AS_STRIDE)
#define QKV_STAGE_B (32*BS_STRIDE)
#define QKV_STAGES 4
#define QKV_SMEM (QKV_STAGES*(QKV_STAGE_A+QKV_STAGE_B)*4)

__device__ __forceinline__ void qkv_load(int tid, int m0, int K0,
                                         const float* __restrict__ x,
                                         uint32_t Aa, uint32_t Ba)
{
    #pragma unroll
    for (int it=0; it<4; it++){
        int i = tid + it*256;
        int r = i>>3, c = i&7;
        cp16(Aa + (uint32_t)(r*AS_STRIDE + c*4)*4u,
             &x[(size_t)(m0+r)*C_ + K0 + c*4]);
    }
    #pragma unroll
    for (int it=0; it<6; it++){
        int i = tid + it*256;
        int r = i/48, c = i%48;
        cp16(Ba + (uint32_t)(r*BS_STRIDE + c*4)*4u,
             &g_wt[(size_t)(K0+r)*192 + c*4]);
    }
    CP_COMMIT();
}

__global__ __launch_bounds__(256) void qkv_kernel(const float* __restrict__ x)
{
    extern __shared__ float sm[];
    float* Asm = sm;
    float* Bsm = sm + QKV_STAGES*QKV_STAGE_A;
    const uint32_t aA = su32(Asm), aB = su32(Bsm);

    const int tid  = threadIdx.x;
    const int lane = tid & 31, warp = tid >> 5;
    const int wm = warp & 3, wn = warp >> 2;
    const int g = lane >> 2, q = lane & 3;
    const int m0 = blockIdx.x * 128;

    float acc[2][12][4];
    #pragma unroll
    for (int mi=0;mi<2;mi++)
        #pragma unroll
        for (int j=0;j<12;j++){acc[mi][j][0]=acc[mi][j][1]=acc[mi][j][2]=acc[mi][j][3]=0.f;}

    qkv_load(tid, m0, 0,  x, aA,                    aB);
    qkv_load(tid, m0, 32, x, aA + QKV_STAGE_A*4u,   aB + QKV_STAGE_B*4u);
    qkv_load(tid, m0, 64, x, aA + 2*QKV_STAGE_A*4u, aB + 2*QKV_STAGE_B*4u);

    #pragma unroll 1
    for (int c = 0; c < 32; c++){
        if (c < 30)      { CP_WAIT(2); }
        else if (c == 30){ CP_WAIT(1); }
        else             { CP_WAIT(0); }
        __syncthreads();
        if (c + 3 < 32){
            int st = (c+3) & 3;
            qkv_load(tid, m0, (c+3)*32, x,
                     aA + (uint32_t)st*QKV_STAGE_A*4u,
                     aB + (uint32_t)st*QKV_STAGE_B*4u);
        }
        const float* A  = Asm + (c & 3)*QKV_STAGE_A;
        const float* Bb = Bsm + (c & 3)*QKV_STAGE_B;
        #pragma unroll
        for (int kk=0;kk<4;kk++){
            float a[2][4];
            #pragma unroll
            for (int mi=0;mi<2;mi++){
                int base = (wm*32 + mi*16 + g)*AS_STRIDE + kk*8 + q;
                a[mi][0]=tf32r(A[base]);
                a[mi][1]=tf32r(A[base + 8*AS_STRIDE]);
                a[mi][2]=tf32r(A[base + 4]);
                a[mi][3]=tf32r(A[base + 8*AS_STRIDE + 4]);
            }
            #pragma unroll
            for (int j=0;j<12;j++){
                float b[2]; int bc = wn*96 + j*8 + g;
                b[0]=Bb[(kk*8+q)*BS_STRIDE + bc];
                b[1]=Bb[(kk*8+q+4)*BS_STRIDE + bc];
                mma_tf32(acc[0][j], a[0], b, acc[0][j]);
                mma_tf32(acc[1][j], a[1], b, acc[1][j]);
            }
        }
    }

    #pragma unroll
    for (int mi=0;mi<2;mi++){
        #pragma unroll
        for (int j=0;j<12;j++){
            int n  = wn*96 + j*8 + q*2;
            int r0 = m0 + wm*32 + mi*16 + g;
            float* dst = (n < 64) ? g_q : ((n < 128) ? g_k : g_v);
            int nn     = (n < 64) ? n   : ((n < 128) ? n-64 : n-128);
            *(float2*)&dst[(size_t)r0*H_ + nn] =
                make_float2(tf32r(acc[mi][j][0]), tf32r(acc[mi][j][1]));
            *(float2*)&dst[(size_t)(r0+8)*H_ + nn] =
                make_float2(tf32r(acc[mi][j][2]), tf32r(acc[mi][j][3]));
        }
    }
}

// ---------------------------------------------------------------------------
// Flash attention: 128 query rows / CTA (32 per warp), causal, tf32 mma,
// cross-CTA split-K by 4, cp.async K double-buffered + V single-buffered.
// bb fragments amortized over 2 M-frags per warp (halves crossbar reads/row).
// smem: Q/P 8704f | K0 4352f | K1 4352f | V 4608f = 88064 B -> 2 CTAs/SM
// ---------------------------------------------------------------------------
#define PS_STRIDE 68
#define KS_STRIDE 68
#define VS_STRIDE 72
#define ATTN_SMEM ((8704 + 2*4352 + 4608)*4)
#define MASKV (-3.0e38f)

__device__ __forceinline__ void attn_ldtile(int tid, const float* __restrict__ src,
                                            uint32_t dst, int stride)
{
    #pragma unroll
    for (int it=0; it<8; it++){
        int i = tid + it*128;
        int r = i>>4, c = i&15;
        cp16(dst + (uint32_t)(r*stride + c*4)*4u, &src[(size_t)r*H_ + c*4]);
    }
    CP_COMMIT();
}

__global__ __launch_bounds__(128) void attn_kernel()
{
    extern __shared__ float sm[];
    float* Qs = sm;                        // Q staging (128 rows), then P
    float* Kb[2] = { sm + 8704, sm + 13056 };
    float* Vs = sm + 17408;
    const uint32_t aK0 = su32(Kb[0]), aK1 = su32(Kb[1]), aV = su32(Vs);

    const int tid  = threadIdx.x;
    const int lane = tid & 31, w = tid >> 5;
    const int g = lane >> 2, q = lane & 3;
    const int qt = (T_/128 - 1) - blockIdx.x;   // heavy blocks first
    const int b  = blockIdx.y;
    const int sp = blockIdx.z;
    const int q0 = qt * 128;

    const float* Qg = g_q + ((size_t)b*T_ + q0)*H_;
    const float* Kg = g_k + (size_t)b*T_*H_;
    const float* Vg = g_v + (size_t)b*T_*H_;

    // key tiles: jt = sp, sp+4, ... <= 2*qt+1
    const int jmax = 2*qt + 1;
    const int ntiles = (jmax >= sp) ? ((jmax - sp) >> 2) + 1 : 0;

    // stage Q: 128 rows x 64 cols
    #pragma unroll
    for (int it=0; it<16; it++){
        int i = tid + it*128;
        int r = i>>4, c4 = (i&15)*4;
        *(float4*)&Qs[r*PS_STRIDE + c4] = *(const float4*)&Qg[(size_t)r*H_ + c4];
    }
    __syncthreads();

    // hoist Q fragments for both M-frags (rows w*32+mf*16+g, +8)
    float qa[2][8][4];
    #pragma unroll
    for (int mf=0; mf<2; mf++){
        #pragma unroll
        for (int kk=0;kk<8;kk++){
            int base = (w*32 + mf*16 + g)*PS_STRIDE + kk*8 + q;
            qa[mf][kk][0]=Qs[base];
            qa[mf][kk][1]=Qs[base + 8*PS_STRIDE];
            qa[mf][kk][2]=Qs[base + 4];
            qa[mf][kk][3]=Qs[base + 8*PS_STRIDE + 4];
        }
    }
    __syncthreads();   // Qs now reusable as P

    float O[2][8][4];
    #pragma unroll
    for (int mf=0;mf<2;mf++)
        #pragma unroll
        for (int j=0;j<8;j++){O[mf][j][0]=O[mf][j][1]=O[mf][j][2]=O[mf][j][3]=0.f;}
    float mst[2][2] = {{-1e30f,-1e30f},{-1e30f,-1e30f}};
    float lst[2][2] = {{0.f,0.f},{0.f,0.f}};

    if (ntiles > 0)
        attn_ldtile(tid, Kg + (size_t)sp*64*H_, aK0, KS_STRIDE);

    #pragma unroll 1
    for (int t = 0; t < ntiles; t++){
        const int jt = sp + t*NSPLIT;
        const int k0 = jt*64;

        CP_WAIT(0);
        __syncthreads();

        attn_ldtile(tid, Vg + (size_t)k0*H_, aV, VS_STRIDE);
        if (t + 1 < ntiles)
            attn_ldtile(tid, Kg + (size_t)(k0 + NSPLIT*64)*H_, (t&1)?aK0:aK1, KS_STRIDE);

        const float* Ks = Kb[t & 1];

        // S = Q K^T for both M-frags, sharing bb loads
        float sreg[2][8][4];
        #pragma unroll
        for (int mf=0;mf<2;mf++)
            #pragma unroll
            for (int j=0;j<8;j++){sreg[mf][j][0]=sreg[mf][j][1]=sreg[mf][j][2]=sreg[mf][j][3]=0.f;}
        #pragma unroll
        for (int kk=0;kk<8;kk++){
            #pragma unroll
            for (int j=0;j<8;j++){
                float bb[2];
                int n = j*8 + g;
                bb[0]=Ks[n*KS_STRIDE + kk*8 + q];
                bb[1]=Ks[n*KS_STRIDE + kk*8 + q + 4];
                mma_tf32(sreg[0][j], qa[0][kk], bb, sreg[0][j]);
                mma_tf32(sreg[1][j], qa[1][kk], bb, sreg[1][j]);
            }
        }

        // causal mask on the two diagonal tiles (jt >= 2*qt).
        // MASKV=-3e38 so fully-masked rows yield p==0 even while m==-1e30.
        if (jt >= 2*qt){
            #pragma unroll
            for (int mf=0;mf<2;mf++){
                #pragma unroll
                for (int j=0;j<8;j++){
                    int gc0 = k0 + j*8 + 2*q, gc1 = gc0+1;
                    int gr0 = q0 + w*32 + mf*16 + g, gr1 = gr0+8;
                    if (gc0 > gr0) sreg[mf][j][0] = MASKV;
                    if (gc1 > gr0) sreg[mf][j][1] = MASKV;
                    if (gc0 > gr1) sreg[mf][j][2] = MASKV;
                    if (gc1 > gr1) sreg[mf][j][3] = MASKV;
                }
            }
        }

        // online softmax (exp2 domain), per M-frag
        #pragma unroll
        for (int mf=0;mf<2;mf++){
            float mx0=-1e30f, mx1=-1e30f;
            #pragma unroll
            for (int j=0;j<8;j++){
                mx0 = fmaxf(mx0, fmaxf(sreg[mf][j][0], sreg[mf][j][1]));
                mx1 = fmaxf(mx1, fmaxf(sreg[mf][j][2], sreg[mf][j][3]));
            }
            mx0 = fmaxf(mx0, __shfl_xor_sync(0xffffffffu, mx0, 1));
            mx0 = fmaxf(mx0, __shfl_xor_sync(0xffffffffu, mx0, 2));
            mx1 = fmaxf(mx1, __shfl_xor_sync(0xffffffffu, mx1, 1));
            mx1 = fmaxf(mx1, __shfl_xor_sync(0xffffffffu, mx1, 2));

            float mn0 = fmaxf(mst[mf][0], mx0), mn1 = fmaxf(mst[mf][1], mx1);
            float al0 = exp2f(mst[mf][0] - mn0), al1 = exp2f(mst[mf][1] - mn1);
            mst[mf][0] = mn0; mst[mf][1] = mn1;
            lst[mf][0] *= al0; lst[mf][1] *= al1;

            float rs0=0.f, rs1=0.f;
            #pragma unroll
            for (int j=0;j<8;j++){
                float p0 = exp2f(sreg[mf][j][0]-mn0), p1 = exp2f(sreg[mf][j][1]-mn0);
                float p2 = exp2f(sreg[mf][j][2]-mn1), p3 = exp2f(sreg[mf][j][3]-mn1);
                rs0 += p0+p1; rs1 += p2+p3;
                O[mf][j][0]*=al0; O[mf][j][1]*=al0; O[mf][j][2]*=al1; O[mf][j][3]*=al1;
                int rbase = (w*32 + mf*16 + g)*PS_STRIDE + j*8 + 2*q;
                *(float2*)&Qs[rbase]               = make_float2(tf32r(p0), tf32r(p1));
                *(float2*)&Qs[rbase + 8*PS_STRIDE] = make_float2(tf32r(p2), tf32r(p3));
            }
            rs0 += __shfl_xor_sync(0xffffffffu, rs0, 1);
            rs0 += __shfl_xor_sync(0xffffffffu, rs0, 2);
            rs1 += __shfl_xor_sync(0xffffffffu, rs1, 1);
            rs1 += __shfl_xor_sync(0xffffffffu, rs1, 2);
            lst[mf][0] += rs0; lst[mf][1] += rs1;
        }

        if (t + 1 < ntiles) { CP_WAIT(1); } else { CP_WAIT(0); }
        __syncthreads();   // V ready; P visible (own-warp rows anyway)

        // O += P V, sharing bbv loads across M-frags
        #pragma unroll
        for (int kk=0;kk<8;kk++){
            float pa[2][4];
            #pragma unroll
            for (int mf=0;mf<2;mf++){
                int base = (w*32 + mf*16 + g)*PS_STRIDE + kk*8 + q;
                pa[mf][0]=Qs[base];
                pa[mf][1]=Qs[base + 8*PS_STRIDE];
                pa[mf][2]=Qs[base + 4];
                pa[mf][3]=Qs[base + 8*PS_STRIDE + 4];
            }
            #pragma unroll
            for (int j=0;j<8;j++){
                float bb[2];
                int hh = j*8 + g;
                bb[0]=Vs[(kk*8+q)*VS_STRIDE   + hh];
                bb[1]=Vs[(kk*8+q+4)*VS_STRIDE + hh];
                mma_tf32(O[0][j], pa[0], bb, O[0][j]);
                mma_tf32(O[1][j], pa[1], bb, O[1][j]);
            }
        }
    }

    // write unnormalized partials + (m, l)
    #pragma unroll
    for (int mf=0;mf<2;mf++){
        const size_t rg0 = (size_t)b*T_ + q0 + w*32 + mf*16 + g;
        float* Po = g_po + (size_t)sp*M_*H_ + rg0*H_;
        #pragma unroll
        for (int j=0;j<8;j++){
            *(float2*)&Po[j*8 + 2*q]        = make_float2(O[mf][j][0], O[mf][j][1]);
            *(float2*)&Po[8*H_ + j*8 + 2*q] = make_float2(O[mf][j][2], O[mf][j][3]);
        }
        if (q == 0){
            float* ml = g_ml + (size_t)sp*M_*2;
            ml[rg0*2]     = mst[mf][0];  ml[rg0*2 + 1]     = lst[mf][0];
            ml[(rg0+8)*2] = mst[mf][1];  ml[(rg0+8)*2 + 1] = lst[mf][1];
        }
    }
}

// ---------------------------------------------------------------------------
// Merge the NSPLIT partials: 2 float4 per thread (same row), MLP 8.
// ---------------------------------------------------------------------------
__global__ __launch_bounds__(256) void merge_kernel(float* __restrict__ out)
{
    const int i2   = blockIdx.x*256 + threadIdx.x;   // [0, M_*H_/8)
    const int idx4 = i2*2;                           // two consecutive float4s
    const int row  = idx4 >> 4;
    float m[NSPLIT], l[NSPLIT], M = -1e30f;
    #pragma unroll
    for (int s=0;s<NSPLIT;s++){
        float2 ml = *(const float2*)&g_ml[(size_t)s*M_*2 + row*2];
        m[s] = ml.x; l[s] = ml.y;
        M = fmaxf(M, m[s]);
    }
    float4 n0 = make_float4(0.f,0.f,0.f,0.f);
    float4 n1 = make_float4(0.f,0.f,0.f,0.f);
    float den = 0.f;
    #pragma unroll
    for (int s=0;s<NSPLIT;s++){
        float e = exp2f(m[s] - M);
        den += l[s]*e;
        float4 p0 = *(const float4*)&g_po[(size_t)s*M_*H_ + idx4*4];
        float4 p1 = *(const float4*)&g_po[(size_t)s*M_*H_ + idx4*4 + 4];
        n0.x += p0.x*e; n0.y += p0.y*e; n0.z += p0.z*e; n0.w += p0.w*e;
        n1.x += p1.x*e; n1.y += p1.y*e; n1.z += p1.z*e; n1.w += p1.w*e;
    }
    float inv = 1.f/den;
    *(float4*)&out[idx4*4]     = make_float4(n0.x*inv, n0.y*inv, n0.z*inv, n0.w*inv);
    *(float4*)&out[idx4*4 + 4] = make_float4(n1.x*inv, n1.y*inv, n1.z*inv, n1.w*inv);
}

extern "C" void kernel_launch(void* const* d_in, const int* in_sizes, int n_in,
                              void* d_out, int out_size)
{
    const float* x  = (const float*)d_in[0];
    const float* wq = (const float*)d_in[1];
    const float* wk = (const float*)d_in[2];
    const float* wv = (const float*)d_in[3];
    float* out = (float*)d_out;

    cudaFuncSetAttribute(qkv_kernel,
                         cudaFuncAttributeMaxDynamicSharedMemorySize, QKV_SMEM);
    cudaFuncSetAttribute(attn_kernel,
                         cudaFuncAttributeMaxDynamicSharedMemorySize, ATTN_SMEM);

    wconv_kernel<<<1024, 192>>>(wq, wk, wv);
    qkv_kernel<<<M_/128, 256, QKV_SMEM>>>(x);
    dim3 grid(T_/128, B_, NSPLIT);
    attn_kernel<<<grid, 128, ATTN_SMEM>>>();
    merge_kernel<<<(M_*H_)/2048, 256>>>(out);
}

// round 12
// speedup vs baseline: 2.9202x; 1.0751x over previous
#include <cuda_runtime.h>
#include <cstdint>

#define B_ 8
#define T_ 2048
#define C_ 1024
#define H_ 64
#define M_ (B_*T_)   // 16384
#define NSPLIT 4

__device__ unsigned g_qb[M_*32];     // q bf16 pairs (scale*log2e folded)
__device__ unsigned g_kb[M_*32];     // k bf16 pairs
__device__ float    g_v [M_*H_];     // v fp32 (tf32-rounded)
__device__ float g_wt[1024*192];
__device__ float g_po[NSPLIT*M_*H_];
__device__ float g_ml[NSPLIT*M_*2];

__device__ __forceinline__ float tf32r(float x){
    asm("cvt.rna.tf32.f32 %0, %0;" : "+f"(x));
    return x;
}
__device__ __forceinline__ unsigned bf2(float lo, float hi){
    unsigned r;
    asm("cvt.rn.bf16x2.f32 %0, %1, %2;" : "=r"(r) : "f"(hi), "f"(lo));
    return r;
}
__device__ __forceinline__ uint32_t su32(const void* p){
    uint32_t a;
    asm("{ .reg .u64 t; cvta.to.shared.u64 t, %1; cvt.u32.u64 %0, t; }" : "=r"(a) : "l"(p));
    return a;
}
__device__ __forceinline__ void cp16(uint32_t dst, const void* src){
    asm volatile("cp.async.cg.shared.global [%0], [%1], 16;" :: "r"(dst), "l"(src) : "memory");
}
#define CP_COMMIT() asm volatile("cp.async.commit_group;" ::: "memory")
#define CP_WAIT(n)  asm volatile("cp.async.wait_group %0;" :: "n"(n) : "memory")

__device__ __forceinline__ void mma_tf32(float* d, const float* a, const float* b, const float* c){
    asm volatile("mma.sync.aligned.m16n8k8.row.col.f32.tf32.tf32.f32 "
        "{%0,%1,%2,%3}, {%4,%5,%6,%7}, {%8,%9}, {%10,%11,%12,%13};"
        : "=f"(d[0]),"=f"(d[1]),"=f"(d[2]),"=f"(d[3])
        : "r"(__float_as_uint(a[0])),"r"(__float_as_uint(a[1])),
          "r"(__float_as_uint(a[2])),"r"(__float_as_uint(a[3])),
          "r"(__float_as_uint(b[0])),"r"(__float_as_uint(b[1])),
          "f"(c[0]),"f"(c[1]),"f"(c[2]),"f"(c[3]));
}
__device__ __forceinline__ void mma_bf16(float* d, const unsigned* a, const unsigned* b, const float* c){
    asm volatile("mma.sync.aligned.m16n8k16.row.col.f32.bf16.bf16.f32 "
        "{%0,%1,%2,%3}, {%4,%5,%6,%7}, {%8,%9}, {%10,%11,%12,%13};"
        : "=f"(d[0]),"=f"(d[1]),"=f"(d[2]),"=f"(d[3])
        : "r"(a[0]),"r"(a[1]),"r"(a[2]),"r"(a[3]),
          "r"(b[0]),"r"(b[1]),
          "f"(c[0]),"f"(c[1]),"f"(c[2]),"f"(c[3]));
}

// ---------------------------------------------------------------------------
// Weight fuse/convert (q-scale * log2e folded).
// ---------------------------------------------------------------------------
__global__ __launch_bounds__(192) void wconv_kernel(
    const float* __restrict__ wq, const float* __restrict__ wk,
    const float* __restrict__ wv)
{
    const int k = blockIdx.x;
    const int n = threadIdx.x;
    const float QSCALE = 0.03125f * 1.44269504f;
    float v = (n < 64) ? wq[k*H_ + n] * QSCALE
            : (n < 128) ? wk[k*H_ + n - 64]
                        : wv[k*H_ + n - 128];
    g_wt[k*192 + n] = tf32r(v);
}

// ---------------------------------------------------------------------------
// Fused QKV projection (tf32 math): epilogue packs q,k to bf16, v stays fp32.
// ---------------------------------------------------------------------------
#define AS_STRIDE 36
#define BS_STRIDE 200
#define QKV_STAGE_A (128*AS_STRIDE)
#define QKV_STAGE_B (32*BS_STRIDE)
#define QKV_STAGES 4
#define QKV_SMEM (QKV_STAGES*(QKV_STAGE_A+QKV_STAGE_B)*4)

__device__ __forceinline__ void qkv_load(int tid, int m0, int K0,
                                         const float* __restrict__ x,
                                         uint32_t Aa, uint32_t Ba)
{
    #pragma unroll
    for (int it=0; it<4; it++){
        int i = tid + it*256;
        int r = i>>3, c = i&7;
        cp16(Aa + (uint32_t)(r*AS_STRIDE + c*4)*4u,
             &x[(size_t)(m0+r)*C_ + K0 + c*4]);
    }
    #pragma unroll
    for (int it=0; it<6; it++){
        int i = tid + it*256;
        int r = i/48, c = i%48;
        cp16(Ba + (uint32_t)(r*BS_STRIDE + c*4)*4u,
             &g_wt[(size_t)(K0+r)*192 + c*4]);
    }
    CP_COMMIT();
}

__global__ __launch_bounds__(256) void qkv_kernel(const float* __restrict__ x)
{
    extern __shared__ float sm[];
    float* Asm = sm;
    float* Bsm = sm + QKV_STAGES*QKV_STAGE_A;
    const uint32_t aA = su32(Asm), aB = su32(Bsm);

    const int tid  = threadIdx.x;
    const int lane = tid & 31, warp = tid >> 5;
    const int wm = warp & 3, wn = warp >> 2;
    const int g = lane >> 2, q = lane & 3;
    const int m0 = blockIdx.x * 128;

    float acc[2][12][4];
    #pragma unroll
    for (int mi=0;mi<2;mi++)
        #pragma unroll
        for (int j=0;j<12;j++){acc[mi][j][0]=acc[mi][j][1]=acc[mi][j][2]=acc[mi][j][3]=0.f;}

    qkv_load(tid, m0, 0,  x, aA,                    aB);
    qkv_load(tid, m0, 32, x, aA + QKV_STAGE_A*4u,   aB + QKV_STAGE_B*4u);
    qkv_load(tid, m0, 64, x, aA + 2*QKV_STAGE_A*4u, aB + 2*QKV_STAGE_B*4u);

    #pragma unroll 1
    for (int c = 0; c < 32; c++){
        if (c < 30)      { CP_WAIT(2); }
        else if (c == 30){ CP_WAIT(1); }
        else             { CP_WAIT(0); }
        __syncthreads();
        if (c + 3 < 32){
            int st = (c+3) & 3;
            qkv_load(tid, m0, (c+3)*32, x,
                     aA + (uint32_t)st*QKV_STAGE_A*4u,
                     aB + (uint32_t)st*QKV_STAGE_B*4u);
        }
        const float* A  = Asm + (c & 3)*QKV_STAGE_A;
        const float* Bb = Bsm + (c & 3)*QKV_STAGE_B;
        #pragma unroll
        for (int kk=0;kk<4;kk++){
            float a[2][4];
            #pragma unroll
            for (int mi=0;mi<2;mi++){
                int base = (wm*32 + mi*16 + g)*AS_STRIDE + kk*8 + q;
                a[mi][0]=tf32r(A[base]);
                a[mi][1]=tf32r(A[base + 8*AS_STRIDE]);
                a[mi][2]=tf32r(A[base + 4]);
                a[mi][3]=tf32r(A[base + 8*AS_STRIDE + 4]);
            }
            #pragma unroll
            for (int j=0;j<12;j++){
                float b[2]; int bc = wn*96 + j*8 + g;
                b[0]=Bb[(kk*8+q)*BS_STRIDE + bc];
                b[1]=Bb[(kk*8+q+4)*BS_STRIDE + bc];
                mma_tf32(acc[0][j], a[0], b, acc[0][j]);
                mma_tf32(acc[1][j], a[1], b, acc[1][j]);
            }
        }
    }

    // epilogue: q,k -> bf16 pairs; v -> fp32 tf32-rounded
    #pragma unroll
    for (int mi=0;mi<2;mi++){
        #pragma unroll
        for (int j=0;j<12;j++){
            int n  = wn*96 + j*8 + q*2;
            int r0 = m0 + wm*32 + mi*16 + g;
            if (n < 128){
                unsigned* dst = (n < 64) ? g_qb : g_kb;
                int nn = (n < 64) ? n : n-64;
                dst[(size_t)r0*32 + (nn>>1)]     = bf2(acc[mi][j][0], acc[mi][j][1]);
                dst[(size_t)(r0+8)*32 + (nn>>1)] = bf2(acc[mi][j][2], acc[mi][j][3]);
            } else {
                int nn = n - 128;
                *(float2*)&g_v[(size_t)r0*H_ + nn] =
                    make_float2(tf32r(acc[mi][j][0]), tf32r(acc[mi][j][1]));
                *(float2*)&g_v[(size_t)(r0+8)*H_ + nn] =
                    make_float2(tf32r(acc[mi][j][2]), tf32r(acc[mi][j][3]));
            }
        }
    }
}

// ---------------------------------------------------------------------------
// Flash attention, hybrid precision: S = QK^T in bf16 m16n8k16,
// PV in tf32 (fp32 V, fp32 P) — the accuracy-critical path.
// 128 rows/CTA (32/warp), cross-CTA split-K by 4, cp.async pipeline.
// smem words: Ps 8704 (fp32 P; Q bf16 staged in first 4608) |
//             K0/K1 2304 u32 each | V 4608 f  = 17920 words = 71680 B
// ---------------------------------------------------------------------------
#define PS_STRIDE 68
#define VS_STRIDE 72
#define ATTN_SMEM (17920*4)
#define MASKV (-3.0e38f)

__global__ __launch_bounds__(128) void attn_kernel()
{
    extern __shared__ float sm[];
    float*    Ps = sm;                          // fp32 P; Q bf16 staging initially
    unsigned* Qu = (unsigned*)sm;
    unsigned* Kb[2] = { (unsigned*)(sm + 8704), (unsigned*)(sm + 11008) };
    float*    Vs = sm + 13312;
    const uint32_t aKb[2] = { su32(Kb[0]), su32(Kb[1]) };
    const uint32_t aV = su32(Vs);

    const int tid  = threadIdx.x;
    const int lane = tid & 31, w = tid >> 5;
    const int g = lane >> 2, q = lane & 3;
    const int qt = (T_/128 - 1) - blockIdx.x;   // heavy blocks first
    const int b  = blockIdx.y;
    const int sp = blockIdx.z;
    const int q0 = qt * 128;

    const unsigned* Qg = g_qb + ((size_t)b*T_ + q0)*32;
    const unsigned* Kg = g_kb + (size_t)b*T_*32;
    const float*    Vg = g_v  + (size_t)b*T_*H_;

    const int jmax = 2*qt + 1;
    const int ntiles = (jmax >= sp) ? ((jmax - sp) >> 2) + 1 : 0;

    // stage Q bf16 (128 rows x 32 u32), plain loads
    #pragma unroll
    for (int it=0; it<8; it++){
        int i = tid + it*128;
        int r = i>>3, c4 = (i&7)*4;
        *(uint4*)&Qu[r*36 + c4] = *(const uint4*)&Qg[(size_t)r*32 + c4];
    }
    __syncthreads();

    // hoist Q bf16 A-fragments
    unsigned qa[2][4][4];
    #pragma unroll
    for (int mf=0; mf<2; mf++){
        #pragma unroll
        for (int kk=0;kk<4;kk++){
            int base = (w*32 + mf*16 + g)*36 + kk*8 + q;
            qa[mf][kk][0]=Qu[base];
            qa[mf][kk][1]=Qu[base + 8*36];
            qa[mf][kk][2]=Qu[base + 4];
            qa[mf][kk][3]=Qu[base + 8*36 + 4];
        }
    }
    __syncthreads();   // region now reusable as fp32 P

    float O[2][8][4];
    #pragma unroll
    for (int mf=0;mf<2;mf++)
        #pragma unroll
        for (int j=0;j<8;j++){O[mf][j][0]=O[mf][j][1]=O[mf][j][2]=O[mf][j][3]=0.f;}
    float mst[2][2] = {{-1e30f,-1e30f},{-1e30f,-1e30f}};
    float lst[2][2] = {{0.f,0.f},{0.f,0.f}};

    if (ntiles > 0){
        #pragma unroll
        for (int it=0; it<4; it++){
            int i = tid + it*128;
            int r = i>>3, c = i&7;
            cp16(aKb[0] + (uint32_t)(r*36 + c*4)*4u, &Kg[(size_t)(sp*64+r)*32 + c*4]);
        }
        CP_COMMIT();
    }

    #pragma unroll 1
    for (int t = 0; t < ntiles; t++){
        const int jt = sp + t*NSPLIT;
        const int k0 = jt*64;

        CP_WAIT(0);            // K(t) ready (and all prior)
        __syncthreads();       // everyone done with prev V / K buffer / P

        // V(t) fp32 (older group), then K(t+1) bf16
        #pragma unroll
        for (int it=0; it<8; it++){
            int i = tid + it*128;
            int r = i>>4, c = i&15;
            cp16(aV + (uint32_t)(r*VS_STRIDE + c*4)*4u, &Vg[(size_t)(k0+r)*H_ + c*4]);
        }
        CP_COMMIT();
        if (t + 1 < ntiles){
            uint32_t aKn = aKb[(t+1)&1];
            #pragma unroll
            for (int it=0; it<4; it++){
                int i = tid + it*128;
                int r = i>>3, c = i&7;
                cp16(aKn + (uint32_t)(r*36 + c*4)*4u,
                     &Kg[(size_t)(k0 + NSPLIT*64 + r)*32 + c*4]);
            }
            CP_COMMIT();
        }

        const unsigned* Ks = Kb[t & 1];

        // S = Q K^T  (bf16 m16n8k16; scale*log2e pre-folded into q)
        float sreg[2][8][4];
        #pragma unroll
        for (int mf=0;mf<2;mf++)
            #pragma unroll
            for (int j=0;j<8;j++){sreg[mf][j][0]=sreg[mf][j][1]=sreg[mf][j][2]=sreg[mf][j][3]=0.f;}
        #pragma unroll
        for (int kk=0;kk<4;kk++){
            #pragma unroll
            for (int j=0;j<8;j++){
                unsigned bb[2];
                int n = j*8 + g;
                bb[0]=Ks[n*36 + kk*8 + q];
                bb[1]=Ks[n*36 + kk*8 + q + 4];
                mma_bf16(sreg[0][j], qa[0][kk], bb, sreg[0][j]);
                mma_bf16(sreg[1][j], qa[1][kk], bb, sreg[1][j]);
            }
        }

        if (jt >= 2*qt){   // diagonal tiles -> causal mask
            #pragma unroll
            for (int mf=0;mf<2;mf++){
                #pragma unroll
                for (int j=0;j<8;j++){
                    int gc0 = k0 + j*8 + 2*q, gc1 = gc0+1;
                    int gr0 = q0 + w*32 + mf*16 + g, gr1 = gr0+8;
                    if (gc0 > gr0) sreg[mf][j][0] = MASKV;
                    if (gc1 > gr0) sreg[mf][j][1] = MASKV;
                    if (gc0 > gr1) sreg[mf][j][2] = MASKV;
                    if (gc1 > gr1) sreg[mf][j][3] = MASKV;
                }
            }
        }

        // online softmax (exp2 domain); P -> fp32 smem (tf32-rounded)
        #pragma unroll
        for (int mf=0;mf<2;mf++){
            float mx0=-1e30f, mx1=-1e30f;
            #pragma unroll
            for (int j=0;j<8;j++){
                mx0 = fmaxf(mx0, fmaxf(sreg[mf][j][0], sreg[mf][j][1]));
                mx1 = fmaxf(mx1, fmaxf(sreg[mf][j][2], sreg[mf][j][3]));
            }
            mx0 = fmaxf(mx0, __shfl_xor_sync(0xffffffffu, mx0, 1));
            mx0 = fmaxf(mx0, __shfl_xor_sync(0xffffffffu, mx0, 2));
            mx1 = fmaxf(mx1, __shfl_xor_sync(0xffffffffu, mx1, 1));
            mx1 = fmaxf(mx1, __shfl_xor_sync(0xffffffffu, mx1, 2));

            float mn0 = fmaxf(mst[mf][0], mx0), mn1 = fmaxf(mst[mf][1], mx1);
            float al0 = exp2f(mst[mf][0] - mn0), al1 = exp2f(mst[mf][1] - mn1);
            mst[mf][0] = mn0; mst[mf][1] = mn1;
            lst[mf][0] *= al0; lst[mf][1] *= al1;

            float rs0=0.f, rs1=0.f;
            #pragma unroll
            for (int j=0;j<8;j++){
                float p0 = exp2f(sreg[mf][j][0]-mn0), p1 = exp2f(sreg[mf][j][1]-mn0);
                float p2 = exp2f(sreg[mf][j][2]-mn1), p3 = exp2f(sreg[mf][j][3]-mn1);
                rs0 += p0+p1; rs1 += p2+p3;
                O[mf][j][0]*=al0; O[mf][j][1]*=al0; O[mf][j][2]*=al1; O[mf][j][3]*=al1;
                int rbase = (w*32 + mf*16 + g)*PS_STRIDE + j*8 + 2*q;
                *(float2*)&Ps[rbase]               = make_float2(tf32r(p0), tf32r(p1));
                *(float2*)&Ps[rbase + 8*PS_STRIDE] = make_float2(tf32r(p2), tf32r(p3));
            }
            rs0 += __shfl_xor_sync(0xffffffffu, rs0, 1);
            rs0 += __shfl_xor_sync(0xffffffffu, rs0, 2);
            rs1 += __shfl_xor_sync(0xffffffffu, rs1, 1);
            rs1 += __shfl_xor_sync(0xffffffffu, rs1, 2);
            lst[mf][0] += rs0; lst[mf][1] += rs1;
        }

        if (t + 1 < ntiles) { CP_WAIT(1); } else { CP_WAIT(0); }
        __syncthreads();   // V(t) visible

        // O += P V  (tf32; shared bb loads across M-frags)
        #pragma unroll
        for (int kk=0;kk<8;kk++){
            float pa[2][4];
            #pragma unroll
            for (int mf=0;mf<2;mf++){
                int base = (w*32 + mf*16 + g)*PS_STRIDE + kk*8 + q;
                pa[mf][0]=Ps[base];
                pa[mf][1]=Ps[base + 8*PS_STRIDE];
                pa[mf][2]=Ps[base + 4];
                pa[mf][3]=Ps[base + 8*PS_STRIDE + 4];
            }
            #pragma unroll
            for (int j=0;j<8;j++){
                float bb[2];
                int hh = j*8 + g;
                bb[0]=Vs[(kk*8+q)*VS_STRIDE   + hh];
                bb[1]=Vs[(kk*8+q+4)*VS_STRIDE + hh];
                mma_tf32(O[0][j], pa[0], bb, O[0][j]);
                mma_tf32(O[1][j], pa[1], bb, O[1][j]);
            }
        }
    }

    // write unnormalized partials + (m, l)
    #pragma unroll
    for (int mf=0;mf<2;mf++){
        const size_t rg0 = (size_t)b*T_ + q0 + w*32 + mf*16 + g;
        float* Po = g_po + (size_t)sp*M_*H_ + rg0*H_;
        #pragma unroll
        for (int j=0;j<8;j++){
            *(float2*)&Po[j*8 + 2*q]        = make_float2(O[mf][j][0], O[mf][j][1]);
            *(float2*)&Po[8*H_ + j*8 + 2*q] = make_float2(O[mf][j][2], O[mf][j][3]);
        }
        if (q == 0){
            float* ml = g_ml + (size_t)sp*M_*2;
            ml[rg0*2]     = mst[mf][0];  ml[rg0*2 + 1]     = lst[mf][0];
            ml[(rg0+8)*2] = mst[mf][1];  ml[(rg0+8)*2 + 1] = lst[mf][1];
        }
    }
}

// ---------------------------------------------------------------------------
// Merge the NSPLIT partials (exp2 domain).
// ---------------------------------------------------------------------------
__global__ __launch_bounds__(256) void merge_kernel(float* __restrict__ out)
{
    const int i2   = blockIdx.x*256 + threadIdx.x;
    const int idx4 = i2*2;
    const int row  = idx4 >> 4;
    float m[NSPLIT], l[NSPLIT], M = -1e30f;
    #pragma unroll
    for (int s=0;s<NSPLIT;s++){
        float2 ml = *(const float2*)&g_ml[(size_t)s*M_*2 + row*2];
        m[s] = ml.x; l[s] = ml.y;
        M = fmaxf(M, m[s]);
    }
    float4 n0 = make_float4(0.f,0.f,0.f,0.f);
    float4 n1 = make_float4(0.f,0.f,0.f,0.f);
    float den = 0.f;
    #pragma unroll
    for (int s=0;s<NSPLIT;s++){
        float e = exp2f(m[s] - M);
        den += l[s]*e;
        float4 p0 = *(const float4*)&g_po[(size_t)s*M_*H_ + idx4*4];
        float4 p1 = *(const float4*)&g_po[(size_t)s*M_*H_ + idx4*4 + 4];
        n0.x += p0.x*e; n0.y += p0.y*e; n0.z += p0.z*e; n0.w += p0.w*e;
        n1.x += p1.x*e; n1.y += p1.y*e; n1.z += p1.z*e; n1.w += p1.w*e;
    }
    float inv = 1.f/den;
    *(float4*)&out[idx4*4]     = make_float4(n0.x*inv, n0.y*inv, n0.z*inv, n0.w*inv);
    *(float4*)&out[idx4*4 + 4] = make_float4(n1.x*inv, n1.y*inv, n1.z*inv, n1.w*inv);
}

extern "C" void kernel_launch(void* const* d_in, const int* in_sizes, int n_in,
                              void* d_out, int out_size)
{
    const float* x  = (const float*)d_in[0];
    const float* wq = (const float*)d_in[1];
    const float* wk = (const float*)d_in[2];
    const float* wv = (const float*)d_in[3];
    float* out = (float*)d_out;

    cudaFuncSetAttribute(qkv_kernel,
                         cudaFuncAttributeMaxDynamicSharedMemorySize, QKV_SMEM);
    cudaFuncSetAttribute(attn_kernel,
                         cudaFuncAttributeMaxDynamicSharedMemorySize, ATTN_SMEM);

    wconv_kernel<<<1024, 192>>>(wq, wk, wv);
    qkv_kernel<<<M_/128, 256, QKV_SMEM>>>(x);
    dim3 grid(T_/128, B_, NSPLIT);
    attn_kernel<<<grid, 128, ATTN_SMEM>>>();
    merge_kernel<<<(M_*H_)/2048, 256>>>(out);
}